// round 1
// baseline (speedup 1.0000x reference)
#include <cuda_runtime.h>
#include <cstdint>
#include <cfloat>

// Problem constants
#define NROWS 16384      // 4*4096 query rows
#define DIM   128
#define KCODES 8192
#define SPLITS 2
#define CPS   (KCODES / SPLITS)   // 4096 codes per split
#define BM    128                 // rows per NN block
#define BN    64                  // codes per smem tile
#define NTILES (CPS / BN)         // 64
#define OUT_Q  0
#define OUT_IND (NROWS * DIM)                 // 2097152
#define OUT_LOSS (NROWS * DIM + NROWS)        // 2113536
#define GATHER_BLOCKS (NROWS / 8)             // 2048

// Scratch (device globals; no allocation allowed)
__device__ float g_xn[NROWS * DIM];     // layernormed x, row-major
__device__ float g_xnT[DIM * NROWS];    // transposed [d][row]
__device__ float g_cbT[DIM * KCODES];   // transposed codebook [d][k]
__device__ float g_e2[KCODES];          // ||e_k||^2
__device__ float g_minval[SPLITS][NROWS];
__device__ int   g_minidx[SPLITS][NROWS];
__device__ float g_part[GATHER_BLOCKS];

// ---------------------------------------------------------------------------
// Kernel A: layernorm rows of x, write g_xn (row-major) and g_xnT (transposed)
// block = 256 threads handles 32 rows; warp w does rows w*4..w*4+3
// ---------------------------------------------------------------------------
__global__ __launch_bounds__(256) void ln_kernel(const float* __restrict__ x) {
    __shared__ float sm[32][129];
    int tid = threadIdx.x, warp = tid >> 5, lane = tid & 31;
    int rowbase = blockIdx.x * 32;

    #pragma unroll
    for (int j = 0; j < 4; j++) {
        int rl = warp * 4 + j;
        int row = rowbase + rl;
        float4 v = *(const float4*)&x[row * DIM + lane * 4];
        float s = v.x + v.y + v.z + v.w;
        #pragma unroll
        for (int o = 16; o > 0; o >>= 1) s += __shfl_xor_sync(0xffffffffu, s, o);
        float mu = s * (1.0f / 128.0f);
        float dx = v.x - mu, dy = v.y - mu, dz = v.z - mu, dw = v.w - mu;
        float q = dx * dx + dy * dy + dz * dz + dw * dw;
        #pragma unroll
        for (int o = 16; o > 0; o >>= 1) q += __shfl_xor_sync(0xffffffffu, q, o);
        float rs = rsqrtf(q * (1.0f / 128.0f) + 1e-5f);
        float4 y = make_float4(dx * rs, dy * rs, dz * rs, dw * rs);
        *(float4*)&g_xn[row * DIM + lane * 4] = y;
        sm[rl][lane * 4 + 0] = y.x;
        sm[rl][lane * 4 + 1] = y.y;
        sm[rl][lane * 4 + 2] = y.z;
        sm[rl][lane * 4 + 3] = y.w;
    }
    __syncthreads();
    // transposed write: 32 rows x 128 d = 4096 elems, 16 per thread, coalesced
    #pragma unroll
    for (int k = 0; k < 16; k++) {
        int idx = k * 256 + tid;
        int d = idx >> 5;
        int r = idx & 31;
        g_xnT[d * NROWS + rowbase + r] = sm[r][d];
    }
}

// ---------------------------------------------------------------------------
// Kernel B: e2[k] = ||codebook[k]||^2, and transposed codebook g_cbT
// ---------------------------------------------------------------------------
__global__ __launch_bounds__(256) void cb_kernel(const float* __restrict__ cb) {
    __shared__ float sm[32][129];
    int tid = threadIdx.x, warp = tid >> 5, lane = tid & 31;
    int rowbase = blockIdx.x * 32;

    #pragma unroll
    for (int j = 0; j < 4; j++) {
        int rl = warp * 4 + j;
        int row = rowbase + rl;
        float4 v = *(const float4*)&cb[row * DIM + lane * 4];
        float q = v.x * v.x + v.y * v.y + v.z * v.z + v.w * v.w;
        #pragma unroll
        for (int o = 16; o > 0; o >>= 1) q += __shfl_xor_sync(0xffffffffu, q, o);
        if (lane == 0) g_e2[row] = q;
        sm[rl][lane * 4 + 0] = v.x;
        sm[rl][lane * 4 + 1] = v.y;
        sm[rl][lane * 4 + 2] = v.z;
        sm[rl][lane * 4 + 3] = v.w;
    }
    __syncthreads();
    #pragma unroll
    for (int k = 0; k < 16; k++) {
        int idx = k * 256 + tid;
        int d = idx >> 5;
        int r = idx & 31;
        g_cbT[d * KCODES + rowbase + r] = sm[r][d];
    }
}

// ---------------------------------------------------------------------------
// Kernel C: fused distance-GEMM + argmin.
// Grid = 128 row-blocks * SPLITS. Block 256 threads, tile BM=128 rows x BN=64
// codes, thread tile 8 rows x 4 codes. dist = e2[k] - 2*dot (x2 constant/row).
// ---------------------------------------------------------------------------
__global__ __launch_bounds__(256, 2) void nn_kernel() {
    extern __shared__ float smem[];
    float* xs = smem;                  // [128][128]  (D-major: xs[d*BM + r])
    float* cs = smem + DIM * BM;       // [128][64]   (cs[d*BN + c])
    float* es = cs + DIM * BN;         // [64]

    int tid = threadIdx.x;
    int rb = blockIdx.x & 127;         // row block
    int sp = blockIdx.x >> 7;          // split
    int row0 = rb * BM;
    int split0 = sp * CPS;

    // load x tile (transposed source -> direct float4, conflict-free)
    #pragma unroll
    for (int k = 0; k < (DIM * BM) / (256 * 4); k++) {  // 16 iters
        int j = k * 256 + tid;
        int d = j >> 5;
        int r4 = (j & 31) << 2;
        *(float4*)&xs[d * BM + r4] = *(const float4*)&g_xnT[d * NROWS + row0 + r4];
    }

    float bestv[8];
    int   besti[8];
    #pragma unroll
    for (int r = 0; r < 8; r++) { bestv[r] = FLT_MAX; besti[r] = 0; }

    int tr = tid >> 4;      // 0..15, 8 rows each
    int tc = tid & 15;      // 0..15, 4 codes each
    const float* xp = xs + tr * 8;
    const float* cp = cs + tc * 4;

    for (int t = 0; t < NTILES; t++) {
        int cb0 = split0 + t * BN;
        __syncthreads();
        #pragma unroll
        for (int k = 0; k < (DIM * BN) / (256 * 4); k++) {  // 8 iters
            int j = k * 256 + tid;
            int d = j >> 4;
            int c4 = (j & 15) << 2;
            *(float4*)&cs[d * BN + c4] = *(const float4*)&g_cbT[d * KCODES + cb0 + c4];
        }
        if (tid < BN) es[tid] = g_e2[cb0 + tid];
        __syncthreads();

        float acc[8][4];
        #pragma unroll
        for (int r = 0; r < 8; r++)
            #pragma unroll
            for (int c = 0; c < 4; c++) acc[r][c] = 0.0f;

        #pragma unroll 4
        for (int d = 0; d < DIM; d++) {
            float4 a0 = *(const float4*)&xp[d * BM];
            float4 a1 = *(const float4*)&xp[d * BM + 4];
            float4 b  = *(const float4*)&cp[d * BN];
            float av[8] = {a0.x, a0.y, a0.z, a0.w, a1.x, a1.y, a1.z, a1.w};
            float bv[4] = {b.x, b.y, b.z, b.w};
            #pragma unroll
            for (int r = 0; r < 8; r++)
                #pragma unroll
                for (int c = 0; c < 4; c++)
                    acc[r][c] = fmaf(av[r], bv[c], acc[r][c]);
        }

        #pragma unroll
        for (int c = 0; c < 4; c++) {
            float e2v = es[tc * 4 + c];
            int code = cb0 + tc * 4 + c;
            #pragma unroll
            for (int r = 0; r < 8; r++) {
                float dist = fmaf(-2.0f, acc[r][c], e2v);
                if (dist < bestv[r]) { bestv[r] = dist; besti[r] = code; }
            }
        }
    }

    // block-level argmin reduction across the 16 tc-threads sharing each row
    __syncthreads();
    float* rv = smem;                       // [BM][16]
    int*   ri = (int*)(smem + BM * 16);     // [BM][16]
    #pragma unroll
    for (int r = 0; r < 8; r++) {
        rv[(tr * 8 + r) * 16 + tc] = bestv[r];
        ri[(tr * 8 + r) * 16 + tc] = besti[r];
    }
    __syncthreads();
    if (tid < BM) {
        float bv = rv[tid * 16];
        int bi = ri[tid * 16];
        #pragma unroll
        for (int j = 1; j < 16; j++) {
            float v = rv[tid * 16 + j];
            int ii = ri[tid * 16 + j];
            if (v < bv || (v == bv && ii < bi)) { bv = v; bi = ii; }
        }
        g_minval[sp][row0 + tid] = bv;
        g_minidx[sp][row0 + tid] = bi;
    }
}

// ---------------------------------------------------------------------------
// Kernel D: combine splits, gather codebook rows into out, write ind as float,
// per-block partial sum of squared diff (deterministic).
// grid = 2048 blocks, 256 threads (1 warp per row, 8 rows/block).
// ---------------------------------------------------------------------------
__global__ __launch_bounds__(256) void gather_kernel(const float* __restrict__ cb,
                                                     float* __restrict__ out) {
    __shared__ float sw[8];
    int warp = threadIdx.x >> 5, lane = threadIdx.x & 31;
    int row = blockIdx.x * 8 + warp;

    float v0 = g_minval[0][row]; int i0 = g_minidx[0][row];
    float v1 = g_minval[1][row]; int i1 = g_minidx[1][row];
    int ind = (v1 < v0 || (v1 == v0 && i1 < i0)) ? i1 : i0;

    float4 c = *(const float4*)&cb[ind * DIM + lane * 4];
    float4 xv = *(const float4*)&g_xn[row * DIM + lane * 4];
    *(float4*)&out[OUT_Q + row * DIM + lane * 4] = c;
    float dx = c.x - xv.x, dy = c.y - xv.y, dz = c.z - xv.z, dw = c.w - xv.w;
    float s = dx * dx + dy * dy + dz * dz + dw * dw;
    #pragma unroll
    for (int o = 16; o > 0; o >>= 1) s += __shfl_xor_sync(0xffffffffu, s, o);
    if (lane == 0) {
        out[OUT_IND + row] = (float)ind;
        sw[warp] = s;
    }
    __syncthreads();
    if (threadIdx.x == 0) {
        float tot = 0.0f;
        #pragma unroll
        for (int w = 0; w < 8; w++) tot += sw[w];
        g_part[blockIdx.x] = tot;
    }
}

// ---------------------------------------------------------------------------
// Kernel E: final deterministic loss reduction
// ---------------------------------------------------------------------------
__global__ __launch_bounds__(256) void final_kernel(float* __restrict__ out) {
    __shared__ float sp[256];
    int tid = threadIdx.x;
    float s = 0.0f;
    for (int i = tid; i < GATHER_BLOCKS; i += 256) s += g_part[i];
    sp[tid] = s;
    __syncthreads();
    for (int o = 128; o > 0; o >>= 1) {
        if (tid < o) sp[tid] += sp[tid + o];
        __syncthreads();
    }
    if (tid == 0) out[OUT_LOSS] = sp[0] * (1.0f / (float)(NROWS * DIM));
}

// ---------------------------------------------------------------------------
extern "C" void kernel_launch(void* const* d_in, const int* in_sizes, int n_in,
                              void* d_out, int out_size) {
    const float* x = (const float*)d_in[0];
    const float* cb = (const float*)d_in[1];
    float* out = (float*)d_out;

    const int smem_bytes = (DIM * BM + DIM * BN + BN) * sizeof(float);  // 98560
    cudaFuncSetAttribute(nn_kernel, cudaFuncAttributeMaxDynamicSharedMemorySize,
                         smem_bytes);

    ln_kernel<<<NROWS / 32, 256>>>(x);
    cb_kernel<<<KCODES / 32, 256>>>(cb);
    nn_kernel<<<128 * SPLITS, 256, smem_bytes>>>();
    gather_kernel<<<GATHER_BLOCKS, 256>>>(cb, out);
    final_kernel<<<1, 256>>>(out);
}

// round 3
// speedup vs baseline: 1.1487x; 1.1487x over previous
#include <cuda_runtime.h>
#include <cuda_bf16.h>
#include <cstdint>
#include <cfloat>

// ---------------------------------------------------------------- constants
#define NROWS  16384
#define DIM    128
#define KCODES 8192
#define NN_CTAS 128          // 128 row-tiles of 128
#define NTILE   64           // 64 code-tiles of 128
#define GATE    0.02f

#define OUT_Q    0
#define OUT_IND  (NROWS * DIM)
#define OUT_LOSS (NROWS * DIM + NROWS)
#define GATHER_BLOCKS (NROWS / 8)

// smem layout (byte offsets). Rows padded: 128 bf16 = 256B data + 16B pad = 272B.
#define ROWB    272
#define BLKB    (128 * ROWB)          // 34816 bytes per [128 x 128bf16] block
#define A_OFF   0                     // 2 blocks (hi, lo) = 69632
#define B_OFF   (2 * BLKB)            // 2 buffers x 2 blocks = 139264
#define E2_OFF  (B_OFF + 4 * BLKB)    // 2 x 512B
#define NN_SMEM (E2_OFF + 1024)       // 209920

// ------------------------------------------------------------- device scratch
__device__ __nv_bfloat16 g_Ahi[NROWS * DIM];
__device__ __nv_bfloat16 g_Alo[NROWS * DIM];
__device__ __nv_bfloat16 g_Bhi[KCODES * DIM];
__device__ __nv_bfloat16 g_Blo[KCODES * DIM];
__device__ float g_xn[NROWS * DIM];
__device__ float g_e2[KCODES];
__device__ float g_b1[NROWS];
__device__ float g_b2[NROWS];
__device__ int   g_i1[NROWS];
__device__ int   g_final[NROWS];
__device__ float g_part[GATHER_BLOCKS];

// ------------------------------------------------------------- PTX helpers
__device__ __forceinline__ uint32_t smem_to_u32(const void* p) {
    uint32_t a;
    asm("{ .reg .u64 t; cvta.to.shared.u64 t, %1; cvt.u32.u64 %0, t; }"
        : "=r"(a) : "l"(p));
    return a;
}
#define CP_ASYNC16(dst, src) \
    asm volatile("cp.async.cg.shared.global [%0], [%1], 16;" \
                 :: "r"(dst), "l"(src) : "memory")
#define CP_COMMIT() asm volatile("cp.async.commit_group;" ::: "memory")
#define CP_WAIT0()  asm volatile("cp.async.wait_group 0;" ::: "memory")

#define LDSM_X4(r0, r1, r2, r3, addr) \
    asm volatile("ldmatrix.sync.aligned.m8n8.x4.shared.b16 {%0,%1,%2,%3}, [%4];" \
                 : "=r"(r0), "=r"(r1), "=r"(r2), "=r"(r3) : "r"(addr))

__device__ __forceinline__ void mma16816(float* c, const uint32_t* a,
                                         uint32_t b0, uint32_t b1) {
    asm volatile(
        "mma.sync.aligned.m16n8k16.row.col.f32.bf16.bf16.f32 "
        "{%0,%1,%2,%3}, {%4,%5,%6,%7}, {%8,%9}, {%0,%1,%2,%3};"
        : "+f"(c[0]), "+f"(c[1]), "+f"(c[2]), "+f"(c[3])
        : "r"(a[0]), "r"(a[1]), "r"(a[2]), "r"(a[3]), "r"(b0), "r"(b1));
}

// ---------------------------------------------------------------------------
// Kernel A: layernorm -> g_xn (f32) + hi/lo bf16 split. 1 row per warp.
// ---------------------------------------------------------------------------
__global__ __launch_bounds__(256) void ln_kernel(const float* __restrict__ x) {
    int warp = threadIdx.x >> 5, lane = threadIdx.x & 31;
    int row = blockIdx.x * 8 + warp;
    float4 v = *(const float4*)&x[(size_t)row * DIM + lane * 4];
    float s = v.x + v.y + v.z + v.w;
    #pragma unroll
    for (int o = 16; o > 0; o >>= 1) s += __shfl_xor_sync(0xffffffffu, s, o);
    float mu = s * (1.0f / 128.0f);
    float dx = v.x - mu, dy = v.y - mu, dz = v.z - mu, dw = v.w - mu;
    float q = dx * dx + dy * dy + dz * dz + dw * dw;
    #pragma unroll
    for (int o = 16; o > 0; o >>= 1) q += __shfl_xor_sync(0xffffffffu, q, o);
    float rs = rsqrtf(q * (1.0f / 128.0f) + 1e-5f);
    float y[4] = {dx * rs, dy * rs, dz * rs, dw * rs};
    *(float4*)&g_xn[(size_t)row * DIM + lane * 4] = make_float4(y[0], y[1], y[2], y[3]);
    __nv_bfloat16 h[4], l[4];
    #pragma unroll
    for (int i = 0; i < 4; i++) {
        h[i] = __float2bfloat16(y[i]);
        l[i] = __float2bfloat16(y[i] - __bfloat162float(h[i]));
    }
    *(uint2*)&g_Ahi[(size_t)row * DIM + lane * 4] = *(uint2*)h;
    *(uint2*)&g_Alo[(size_t)row * DIM + lane * 4] = *(uint2*)l;
}

// ---------------------------------------------------------------------------
// Kernel B: codebook -> e2 (exact f32) + hi/lo bf16 split. 1 code per warp.
// ---------------------------------------------------------------------------
__global__ __launch_bounds__(256) void cb_kernel(const float* __restrict__ cb) {
    int warp = threadIdx.x >> 5, lane = threadIdx.x & 31;
    int row = blockIdx.x * 8 + warp;
    float4 v = *(const float4*)&cb[(size_t)row * DIM + lane * 4];
    float q = v.x * v.x + v.y * v.y + v.z * v.z + v.w * v.w;
    #pragma unroll
    for (int o = 16; o > 0; o >>= 1) q += __shfl_xor_sync(0xffffffffu, q, o);
    if (lane == 0) g_e2[row] = q;
    float y[4] = {v.x, v.y, v.z, v.w};
    __nv_bfloat16 h[4], l[4];
    #pragma unroll
    for (int i = 0; i < 4; i++) {
        h[i] = __float2bfloat16(y[i]);
        l[i] = __float2bfloat16(y[i] - __bfloat162float(h[i]));
    }
    *(uint2*)&g_Bhi[(size_t)row * DIM + lane * 4] = *(uint2*)h;
    *(uint2*)&g_Blo[(size_t)row * DIM + lane * 4] = *(uint2*)l;
}

// ---------------------------------------------------------------------------
// Kernel C: HMMA bf16x3 distance GEMM + per-row top-2.
// 128 CTAs x 256 thr. CTA: 128 rows x all 8192 codes (64 tiles of 128),
// K = 384 (hi*hi | lo*hi | hi*lo), 24 mma k-steps per tile.
// ---------------------------------------------------------------------------
__global__ __launch_bounds__(256, 1) void nn_kernel() {
    extern __shared__ char sptr[];
    const uint32_t sbase = smem_to_u32(sptr);
    const int tid = threadIdx.x;
    const int lane = tid & 31;
    const int w = tid >> 5;
    const int mrow = (w & 3) * 32;          // warp's row offset in tile
    const int ncol0 = (w >> 2) * 64;        // warp's col offset in tile
    const int row0 = blockIdx.x * 128;

    // ---- A tile: plain loads (once). 2 blocks (hi, lo), rows stride 272B.
    #pragma unroll
    for (int i = 0; i < 16; i++) {
        int idx = i * 256 + tid;
        int kb = idx >> 11;
        int r = (idx >> 4) & 127;
        int u = idx & 15;
        const __nv_bfloat16* src =
            (kb ? g_Alo : g_Ahi) + (size_t)(row0 + r) * DIM + u * 8;
        uint4 v = *(const uint4*)src;
        *(uint4*)(sptr + A_OFF + kb * BLKB + r * ROWB + u * 16) = v;
    }
    // ---- B tile 0 via cp.async into buffer 0 (+ e2 slot 0)
    {
        uint32_t bb = sbase + B_OFF;
        #pragma unroll
        for (int i = 0; i < 16; i++) {
            int idx = i * 256 + tid;
            int kb = idx >> 11;
            int r = (idx >> 4) & 127;
            int u = idx & 15;
            const __nv_bfloat16* src =
                (kb ? g_Blo : g_Bhi) + (size_t)r * DIM + u * 8;
            CP_ASYNC16(bb + kb * BLKB + r * ROWB + u * 16, src);
        }
        if (tid < 32) CP_ASYNC16(sbase + E2_OFF + tid * 16, (const char*)g_e2 + tid * 16);
        CP_COMMIT();
    }

    float B1[4], B2[4];
    int I1[4];
    #pragma unroll
    for (int s = 0; s < 4; s++) { B1[s] = FLT_MAX; B2[s] = FLT_MAX; I1[s] = 0; }

    // precomputed ldmatrix lane addressing
    const uint32_t a_row = mrow + (lane & 15);
    const uint32_t a_cb = (lane >> 4) << 4;                 // +16B for k+8 half
    const uint32_t b_row = ncol0 + (lane & 7) + ((lane & 16) >> 1);
    const uint32_t b_k8 = (lane & 8);                       // +8 elems

    for (int t = 0; t < NTILE; t++) {
        CP_WAIT0();
        __syncthreads();
        // issue next tile's loads
        if (t + 1 < NTILE) {
            uint32_t bb = sbase + B_OFF + ((t + 1) & 1) * (2 * BLKB);
            const size_t crow0 = (size_t)(t + 1) * 128;
            #pragma unroll
            for (int i = 0; i < 16; i++) {
                int idx = i * 256 + tid;
                int kb = idx >> 11;
                int r = (idx >> 4) & 127;
                int u = idx & 15;
                const __nv_bfloat16* src =
                    (kb ? g_Blo : g_Bhi) + (crow0 + r) * DIM + u * 8;
                CP_ASYNC16(bb + kb * BLKB + r * ROWB + u * 16, src);
            }
            if (tid < 32)
                CP_ASYNC16(sbase + E2_OFF + ((t + 1) & 1) * 512 + tid * 16,
                           (const char*)(g_e2 + (t + 1) * 128) + tid * 16);
            CP_COMMIT();
        }

        // ---- compute tile t
        const uint32_t bufB = sbase + B_OFF + (t & 1) * (2 * BLKB);
        float c[2][8][4];
        #pragma unroll
        for (int mb = 0; mb < 2; mb++)
            #pragma unroll
            for (int nb = 0; nb < 8; nb++)
                #pragma unroll
                for (int q = 0; q < 4; q++) c[mb][nb][q] = 0.0f;

        #pragma unroll
        for (int j = 0; j < 24; j++) {
            const int asel = ((j >> 3) == 1) ? 1 : 0;   // lo-A for middle 8 steps
            const int bsel = ((j >> 3) == 2) ? 1 : 0;   // lo-B for last 8 steps
            const int kk = (j & 7) * 16;
            uint32_t a[2][4];
            #pragma unroll
            for (int mb = 0; mb < 2; mb++) {
                uint32_t addr = sbase + A_OFF + asel * BLKB +
                                (a_row + mb * 16) * ROWB + kk * 2 + a_cb;
                LDSM_X4(a[mb][0], a[mb][1], a[mb][2], a[mb][3], addr);
            }
            uint32_t b[4][4];
            #pragma unroll
            for (int nb4 = 0; nb4 < 4; nb4++) {
                uint32_t addr = bufB + bsel * BLKB +
                                (b_row + nb4 * 16) * ROWB + (kk + b_k8) * 2;
                LDSM_X4(b[nb4][0], b[nb4][1], b[nb4][2], b[nb4][3], addr);
            }
            #pragma unroll
            for (int mb = 0; mb < 2; mb++)
                #pragma unroll
                for (int nb = 0; nb < 8; nb++)
                    mma16816(c[mb][nb], a[mb],
                             b[nb >> 1][(nb & 1) * 2], b[nb >> 1][(nb & 1) * 2 + 1]);
        }

        // ---- epilogue: dist = e2 - 2*dot, per-row top-2
        const float* e2p = (const float*)(sptr + E2_OFF + (t & 1) * 512);
        const int colb = ncol0 + 2 * (lane & 3);
        #pragma unroll
        for (int nb = 0; nb < 8; nb++) {
            float2 ev = *(const float2*)&e2p[colb + nb * 8];
            int gidx = t * 128 + colb + nb * 8;
            #pragma unroll
            for (int mb = 0; mb < 2; mb++)
                #pragma unroll
                for (int hi = 0; hi < 2; hi++) {
                    int s = mb * 2 + hi;
                    float d0 = fmaf(-2.0f, c[mb][nb][hi * 2 + 0], ev.x);
                    float d1 = fmaf(-2.0f, c[mb][nb][hi * 2 + 1], ev.y);
                    if (d0 < B1[s]) { B2[s] = B1[s]; B1[s] = d0; I1[s] = gidx; }
                    else if (d0 < B2[s]) { B2[s] = d0; }
                    if (d1 < B1[s]) { B2[s] = B1[s]; B1[s] = d1; I1[s] = gidx + 1; }
                    else if (d1 < B2[s]) { B2[s] = d1; }
                }
        }
    }

    // ---- reduce across the 4 lanes sharing each row (xor 1, 2)
    #pragma unroll
    for (int s = 0; s < 4; s++) {
        #pragma unroll
        for (int off = 1; off < 4; off <<= 1) {
            float ob1 = __shfl_xor_sync(0xffffffffu, B1[s], off);
            float ob2 = __shfl_xor_sync(0xffffffffu, B2[s], off);
            int oi1 = __shfl_xor_sync(0xffffffffu, I1[s], off);
            float nb2 = fminf(fminf(B2[s], ob2), fmaxf(B1[s], ob1));
            if (ob1 < B1[s] || (ob1 == B1[s] && oi1 < I1[s])) { B1[s] = ob1; I1[s] = oi1; }
            B2[s] = nb2;
        }
    }
    // ---- merge the two n-half warps via smem (reuse A region)
    __syncthreads();
    float* rv1 = (float*)sptr;          // [128][2]
    float* rv2 = rv1 + 256;             // [128][2]
    int*   ri1 = (int*)(rv2 + 256);     // [128][2]
    if ((lane & 3) == 0) {
        int nh = w >> 2;
        #pragma unroll
        for (int s = 0; s < 4; s++) {
            int rl = mrow + (s >> 1) * 16 + (s & 1) * 8 + (lane >> 2);
            rv1[rl * 2 + nh] = B1[s];
            rv2[rl * 2 + nh] = B2[s];
            ri1[rl * 2 + nh] = I1[s];
        }
    }
    __syncthreads();
    if (tid < 128) {
        float a1 = rv1[tid * 2], a2 = rv2[tid * 2];
        int ai = ri1[tid * 2];
        float o1 = rv1[tid * 2 + 1], o2 = rv2[tid * 2 + 1];
        int oi = ri1[tid * 2 + 1];
        float n2 = fminf(fminf(a2, o2), fmaxf(a1, o1));
        if (o1 < a1 || (o1 == a1 && oi < ai)) { a1 = o1; ai = oi; }
        g_b1[row0 + tid] = a1;
        g_b2[row0 + tid] = n2;
        g_i1[row0 + tid] = ai;
    }
}

// ---------------------------------------------------------------------------
// Kernel D: rescan. One block per row; gated rows do exact fp32 full scan.
// ---------------------------------------------------------------------------
__global__ __launch_bounds__(128) void rescan_kernel(const float* __restrict__ cb) {
    int row = blockIdx.x;
    float gap = g_b2[row] - g_b1[row];
    if (gap >= GATE) {
        if (threadIdx.x == 0) g_final[row] = g_i1[row];
        return;
    }
    __shared__ float xs[DIM];
    __shared__ float rv[128];
    __shared__ int   ri[128];
    int tid = threadIdx.x;
    xs[tid] = g_xn[(size_t)row * DIM + tid];
    __syncthreads();

    float best = FLT_MAX;
    int bidx = 0;
    for (int j = 0; j < KCODES / 128; j++) {
        int c = j * 128 + tid;
        const float4* cp = (const float4*)&cb[(size_t)c * DIM];
        float s0 = 0.f, s1 = 0.f, s2 = 0.f, s3 = 0.f;
        #pragma unroll
        for (int d = 0; d < 32; d += 4) {
            float4 v0 = cp[d + 0], v1 = cp[d + 1], v2 = cp[d + 2], v3 = cp[d + 3];
            s0 = fmaf(v0.x, xs[d * 4 + 0], s0);  s0 = fmaf(v0.y, xs[d * 4 + 1], s0);
            s0 = fmaf(v0.z, xs[d * 4 + 2], s0);  s0 = fmaf(v0.w, xs[d * 4 + 3], s0);
            s1 = fmaf(v1.x, xs[d * 4 + 4], s1);  s1 = fmaf(v1.y, xs[d * 4 + 5], s1);
            s1 = fmaf(v1.z, xs[d * 4 + 6], s1);  s1 = fmaf(v1.w, xs[d * 4 + 7], s1);
            s2 = fmaf(v2.x, xs[d * 4 + 8], s2);  s2 = fmaf(v2.y, xs[d * 4 + 9], s2);
            s2 = fmaf(v2.z, xs[d * 4 + 10], s2); s2 = fmaf(v2.w, xs[d * 4 + 11], s2);
            s3 = fmaf(v3.x, xs[d * 4 + 12], s3); s3 = fmaf(v3.y, xs[d * 4 + 13], s3);
            s3 = fmaf(v3.z, xs[d * 4 + 14], s3); s3 = fmaf(v3.w, xs[d * 4 + 15], s3);
        }
        float dot = (s0 + s1) + (s2 + s3);
        float dist = fmaf(-2.0f, dot, g_e2[c]);
        if (dist < best || (dist == best && c < bidx)) { best = dist; bidx = c; }
    }
    rv[tid] = best; ri[tid] = bidx;
    __syncthreads();
    for (int o = 64; o > 0; o >>= 1) {
        if (tid < o) {
            float v = rv[tid + o]; int ii = ri[tid + o];
            if (v < rv[tid] || (v == rv[tid] && ii < ri[tid])) { rv[tid] = v; ri[tid] = ii; }
        }
        __syncthreads();
    }
    if (tid == 0) g_final[row] = ri[0];
}

// ---------------------------------------------------------------------------
// Kernel E: gather + per-block loss partials (deterministic).
// ---------------------------------------------------------------------------
__global__ __launch_bounds__(256) void gather_kernel(const float* __restrict__ cb,
                                                     float* __restrict__ out) {
    __shared__ float sw[8];
    int warp = threadIdx.x >> 5, lane = threadIdx.x & 31;
    int row = blockIdx.x * 8 + warp;
    int ind = g_final[row];
    float4 c = *(const float4*)&cb[(size_t)ind * DIM + lane * 4];
    float4 xv = *(const float4*)&g_xn[(size_t)row * DIM + lane * 4];
    *(float4*)&out[OUT_Q + (size_t)row * DIM + lane * 4] = c;
    float dx = c.x - xv.x, dy = c.y - xv.y, dz = c.z - xv.z, dw = c.w - xv.w;
    float s = dx * dx + dy * dy + dz * dz + dw * dw;
    #pragma unroll
    for (int o = 16; o > 0; o >>= 1) s += __shfl_xor_sync(0xffffffffu, s, o);
    if (lane == 0) { out[OUT_IND + row] = (float)ind; sw[warp] = s; }
    __syncthreads();
    if (threadIdx.x == 0) {
        float tot = 0.0f;
        #pragma unroll
        for (int w = 0; w < 8; w++) tot += sw[w];
        g_part[blockIdx.x] = tot;
    }
}

__global__ __launch_bounds__(256) void final_kernel(float* __restrict__ out) {
    __shared__ float sp[256];
    int tid = threadIdx.x;
    float s = 0.0f;
    for (int i = tid; i < GATHER_BLOCKS; i += 256) s += g_part[i];
    sp[tid] = s;
    __syncthreads();
    for (int o = 128; o > 0; o >>= 1) {
        if (tid < o) sp[tid] += sp[tid + o];
        __syncthreads();
    }
    if (tid == 0) out[OUT_LOSS] = sp[0] * (1.0f / (float)(NROWS * DIM));
}

// ---------------------------------------------------------------------------
extern "C" void kernel_launch(void* const* d_in, const int* in_sizes, int n_in,
                              void* d_out, int out_size) {
    const float* x = (const float*)d_in[0];
    const float* cb = (const float*)d_in[1];
    float* out = (float*)d_out;

    cudaFuncSetAttribute(nn_kernel, cudaFuncAttributeMaxDynamicSharedMemorySize,
                         NN_SMEM);

    ln_kernel<<<NROWS / 8, 256>>>(x);
    cb_kernel<<<KCODES / 8, 256>>>(cb);
    nn_kernel<<<NN_CTAS, 256, NN_SMEM>>>();
    rescan_kernel<<<NROWS, 128>>>(cb);
    gather_kernel<<<GATHER_BLOCKS, 256>>>(cb, out);
    final_kernel<<<1, 256>>>(out);
}

// round 4
// speedup vs baseline: 1.7483x; 1.5220x over previous
#include <cuda_runtime.h>
#include <cuda_bf16.h>
#include <cstdint>
#include <cfloat>

// ---------------------------------------------------------------- constants
#define NROWS  16384
#define DIM    128
#define KCODES 8192
#define NN_CTAS 128          // 128 row-tiles of 128
#define NTILE   64           // 64 code-tiles of 128
#define GATE    0.02f

#define OUT_Q    0
#define OUT_IND  (NROWS * DIM)
#define OUT_LOSS (NROWS * DIM + NROWS)
#define GATHER_BLOCKS (NROWS / 8)

// rescan config
#define RS_ROWS   16
#define RS_SPLITS 8
#define RS_CPS    (KCODES / RS_SPLITS)    // 1024 codes per split
#define RS_MAXBATCH (NROWS / RS_ROWS)     // 1024
#define RS_GRID   (RS_MAXBATCH * RS_SPLITS)

// smem layout (byte offsets). Rows padded: 128 bf16 = 256B data + 16B pad = 272B.
#define ROWB    272
#define BLKB    (128 * ROWB)          // 34816 bytes per [128 x 128bf16] block
#define A_OFF   0                     // 2 blocks (hi, lo) = 69632
#define B_OFF   (2 * BLKB)            // 2 buffers x 2 blocks = 139264
#define E2_OFF  (B_OFF + 4 * BLKB)    // 2 x 512B
#define NN_SMEM (E2_OFF + 1024)       // 209920

// ------------------------------------------------------------- device scratch
__device__ __nv_bfloat16 g_Ahi[NROWS * DIM];
__device__ __nv_bfloat16 g_Alo[NROWS * DIM];
__device__ __nv_bfloat16 g_Bhi[KCODES * DIM];
__device__ __nv_bfloat16 g_Blo[KCODES * DIM];
__device__ float g_xn[NROWS * DIM];
__device__ float g_e2[KCODES];
__device__ float g_b1[NROWS];
__device__ float g_b2[NROWS];
__device__ int   g_i1[NROWS];
__device__ int   g_final[NROWS];
__device__ float g_part[GATHER_BLOCKS];
__device__ int   g_count;
__device__ int   g_list[NROWS];
__device__ float g_sv[NROWS * RS_SPLITS];
__device__ int   g_si[NROWS * RS_SPLITS];

// ------------------------------------------------------------- PTX helpers
__device__ __forceinline__ uint32_t smem_to_u32(const void* p) {
    uint32_t a;
    asm("{ .reg .u64 t; cvta.to.shared.u64 t, %1; cvt.u32.u64 %0, t; }"
        : "=r"(a) : "l"(p));
    return a;
}
#define CP_ASYNC16(dst, src) \
    asm volatile("cp.async.cg.shared.global [%0], [%1], 16;" \
                 :: "r"(dst), "l"(src) : "memory")
#define CP_COMMIT() asm volatile("cp.async.commit_group;" ::: "memory")
#define CP_WAIT0()  asm volatile("cp.async.wait_group 0;" ::: "memory")

#define LDSM_X4(r0, r1, r2, r3, addr) \
    asm volatile("ldmatrix.sync.aligned.m8n8.x4.shared.b16 {%0,%1,%2,%3}, [%4];" \
                 : "=r"(r0), "=r"(r1), "=r"(r2), "=r"(r3) : "r"(addr))

__device__ __forceinline__ void mma16816(float* c, const uint32_t* a,
                                         uint32_t b0, uint32_t b1) {
    asm volatile(
        "mma.sync.aligned.m16n8k16.row.col.f32.bf16.bf16.f32 "
        "{%0,%1,%2,%3}, {%4,%5,%6,%7}, {%8,%9}, {%0,%1,%2,%3};"
        : "+f"(c[0]), "+f"(c[1]), "+f"(c[2]), "+f"(c[3])
        : "r"(a[0]), "r"(a[1]), "r"(a[2]), "r"(a[3]), "r"(b0), "r"(b1));
}

// ---------------------------------------------------------------------------
// Kernel A: layernorm -> g_xn (f32) + hi/lo bf16 split. 1 row per warp.
// ---------------------------------------------------------------------------
__global__ __launch_bounds__(256) void ln_kernel(const float* __restrict__ x) {
    if (blockIdx.x == 0 && threadIdx.x == 0) g_count = 0;   // reset rescan count
    int warp = threadIdx.x >> 5, lane = threadIdx.x & 31;
    int row = blockIdx.x * 8 + warp;
    float4 v = *(const float4*)&x[(size_t)row * DIM + lane * 4];
    float s = v.x + v.y + v.z + v.w;
    #pragma unroll
    for (int o = 16; o > 0; o >>= 1) s += __shfl_xor_sync(0xffffffffu, s, o);
    float mu = s * (1.0f / 128.0f);
    float dx = v.x - mu, dy = v.y - mu, dz = v.z - mu, dw = v.w - mu;
    float q = dx * dx + dy * dy + dz * dz + dw * dw;
    #pragma unroll
    for (int o = 16; o > 0; o >>= 1) q += __shfl_xor_sync(0xffffffffu, q, o);
    float rs = rsqrtf(q * (1.0f / 128.0f) + 1e-5f);
    float y[4] = {dx * rs, dy * rs, dz * rs, dw * rs};
    *(float4*)&g_xn[(size_t)row * DIM + lane * 4] = make_float4(y[0], y[1], y[2], y[3]);
    __nv_bfloat16 h[4], l[4];
    #pragma unroll
    for (int i = 0; i < 4; i++) {
        h[i] = __float2bfloat16(y[i]);
        l[i] = __float2bfloat16(y[i] - __bfloat162float(h[i]));
    }
    *(uint2*)&g_Ahi[(size_t)row * DIM + lane * 4] = *(uint2*)h;
    *(uint2*)&g_Alo[(size_t)row * DIM + lane * 4] = *(uint2*)l;
}

// ---------------------------------------------------------------------------
// Kernel B: codebook -> e2 (exact f32) + hi/lo bf16 split. 1 code per warp.
// ---------------------------------------------------------------------------
__global__ __launch_bounds__(256) void cb_kernel(const float* __restrict__ cb) {
    int warp = threadIdx.x >> 5, lane = threadIdx.x & 31;
    int row = blockIdx.x * 8 + warp;
    float4 v = *(const float4*)&cb[(size_t)row * DIM + lane * 4];
    float q = v.x * v.x + v.y * v.y + v.z * v.z + v.w * v.w;
    #pragma unroll
    for (int o = 16; o > 0; o >>= 1) q += __shfl_xor_sync(0xffffffffu, q, o);
    if (lane == 0) g_e2[row] = q;
    float y[4] = {v.x, v.y, v.z, v.w};
    __nv_bfloat16 h[4], l[4];
    #pragma unroll
    for (int i = 0; i < 4; i++) {
        h[i] = __float2bfloat16(y[i]);
        l[i] = __float2bfloat16(y[i] - __bfloat162float(h[i]));
    }
    *(uint2*)&g_Bhi[(size_t)row * DIM + lane * 4] = *(uint2*)h;
    *(uint2*)&g_Blo[(size_t)row * DIM + lane * 4] = *(uint2*)l;
}

// ---------------------------------------------------------------------------
// Kernel C: HMMA bf16x3 distance GEMM + per-row top-2. (unchanged from R3)
// ---------------------------------------------------------------------------
__global__ __launch_bounds__(256, 1) void nn_kernel() {
    extern __shared__ char sptr[];
    const uint32_t sbase = smem_to_u32(sptr);
    const int tid = threadIdx.x;
    const int lane = tid & 31;
    const int w = tid >> 5;
    const int mrow = (w & 3) * 32;
    const int ncol0 = (w >> 2) * 64;
    const int row0 = blockIdx.x * 128;

    #pragma unroll
    for (int i = 0; i < 16; i++) {
        int idx = i * 256 + tid;
        int kb = idx >> 11;
        int r = (idx >> 4) & 127;
        int u = idx & 15;
        const __nv_bfloat16* src =
            (kb ? g_Alo : g_Ahi) + (size_t)(row0 + r) * DIM + u * 8;
        uint4 v = *(const uint4*)src;
        *(uint4*)(sptr + A_OFF + kb * BLKB + r * ROWB + u * 16) = v;
    }
    {
        uint32_t bb = sbase + B_OFF;
        #pragma unroll
        for (int i = 0; i < 16; i++) {
            int idx = i * 256 + tid;
            int kb = idx >> 11;
            int r = (idx >> 4) & 127;
            int u = idx & 15;
            const __nv_bfloat16* src =
                (kb ? g_Blo : g_Bhi) + (size_t)r * DIM + u * 8;
            CP_ASYNC16(bb + kb * BLKB + r * ROWB + u * 16, src);
        }
        if (tid < 32) CP_ASYNC16(sbase + E2_OFF + tid * 16, (const char*)g_e2 + tid * 16);
        CP_COMMIT();
    }

    float B1[4], B2[4];
    int I1[4];
    #pragma unroll
    for (int s = 0; s < 4; s++) { B1[s] = FLT_MAX; B2[s] = FLT_MAX; I1[s] = 0; }

    const uint32_t a_row = mrow + (lane & 15);
    const uint32_t a_cb = (lane >> 4) << 4;
    const uint32_t b_row = ncol0 + (lane & 7) + ((lane & 16) >> 1);
    const uint32_t b_k8 = (lane & 8);

    for (int t = 0; t < NTILE; t++) {
        CP_WAIT0();
        __syncthreads();
        if (t + 1 < NTILE) {
            uint32_t bb = sbase + B_OFF + ((t + 1) & 1) * (2 * BLKB);
            const size_t crow0 = (size_t)(t + 1) * 128;
            #pragma unroll
            for (int i = 0; i < 16; i++) {
                int idx = i * 256 + tid;
                int kb = idx >> 11;
                int r = (idx >> 4) & 127;
                int u = idx & 15;
                const __nv_bfloat16* src =
                    (kb ? g_Blo : g_Bhi) + (crow0 + r) * DIM + u * 8;
                CP_ASYNC16(bb + kb * BLKB + r * ROWB + u * 16, src);
            }
            if (tid < 32)
                CP_ASYNC16(sbase + E2_OFF + ((t + 1) & 1) * 512 + tid * 16,
                           (const char*)(g_e2 + (t + 1) * 128) + tid * 16);
            CP_COMMIT();
        }

        const uint32_t bufB = sbase + B_OFF + (t & 1) * (2 * BLKB);
        float c[2][8][4];
        #pragma unroll
        for (int mb = 0; mb < 2; mb++)
            #pragma unroll
            for (int nb = 0; nb < 8; nb++)
                #pragma unroll
                for (int q = 0; q < 4; q++) c[mb][nb][q] = 0.0f;

        #pragma unroll
        for (int j = 0; j < 24; j++) {
            const int asel = ((j >> 3) == 1) ? 1 : 0;
            const int bsel = ((j >> 3) == 2) ? 1 : 0;
            const int kk = (j & 7) * 16;
            uint32_t a[2][4];
            #pragma unroll
            for (int mb = 0; mb < 2; mb++) {
                uint32_t addr = sbase + A_OFF + asel * BLKB +
                                (a_row + mb * 16) * ROWB + kk * 2 + a_cb;
                LDSM_X4(a[mb][0], a[mb][1], a[mb][2], a[mb][3], addr);
            }
            uint32_t b[4][4];
            #pragma unroll
            for (int nb4 = 0; nb4 < 4; nb4++) {
                uint32_t addr = bufB + bsel * BLKB +
                                (b_row + nb4 * 16) * ROWB + (kk + b_k8) * 2;
                LDSM_X4(b[nb4][0], b[nb4][1], b[nb4][2], b[nb4][3], addr);
            }
            #pragma unroll
            for (int mb = 0; mb < 2; mb++)
                #pragma unroll
                for (int nb = 0; nb < 8; nb++)
                    mma16816(c[mb][nb], a[mb],
                             b[nb >> 1][(nb & 1) * 2], b[nb >> 1][(nb & 1) * 2 + 1]);
        }

        const float* e2p = (const float*)(sptr + E2_OFF + (t & 1) * 512);
        const int colb = ncol0 + 2 * (lane & 3);
        #pragma unroll
        for (int nb = 0; nb < 8; nb++) {
            float2 ev = *(const float2*)&e2p[colb + nb * 8];
            int gidx = t * 128 + colb + nb * 8;
            #pragma unroll
            for (int mb = 0; mb < 2; mb++)
                #pragma unroll
                for (int hi = 0; hi < 2; hi++) {
                    int s = mb * 2 + hi;
                    float d0 = fmaf(-2.0f, c[mb][nb][hi * 2 + 0], ev.x);
                    float d1 = fmaf(-2.0f, c[mb][nb][hi * 2 + 1], ev.y);
                    if (d0 < B1[s]) { B2[s] = B1[s]; B1[s] = d0; I1[s] = gidx; }
                    else if (d0 < B2[s]) { B2[s] = d0; }
                    if (d1 < B1[s]) { B2[s] = B1[s]; B1[s] = d1; I1[s] = gidx + 1; }
                    else if (d1 < B2[s]) { B2[s] = d1; }
                }
        }
    }

    #pragma unroll
    for (int s = 0; s < 4; s++) {
        #pragma unroll
        for (int off = 1; off < 4; off <<= 1) {
            float ob1 = __shfl_xor_sync(0xffffffffu, B1[s], off);
            float ob2 = __shfl_xor_sync(0xffffffffu, B2[s], off);
            int oi1 = __shfl_xor_sync(0xffffffffu, I1[s], off);
            float nb2 = fminf(fminf(B2[s], ob2), fmaxf(B1[s], ob1));
            if (ob1 < B1[s] || (ob1 == B1[s] && oi1 < I1[s])) { B1[s] = ob1; I1[s] = oi1; }
            B2[s] = nb2;
        }
    }
    __syncthreads();
    float* rv1 = (float*)sptr;
    float* rv2 = rv1 + 256;
    int*   ri1 = (int*)(rv2 + 256);
    if ((lane & 3) == 0) {
        int nh = w >> 2;
        #pragma unroll
        for (int s = 0; s < 4; s++) {
            int rl = mrow + (s >> 1) * 16 + (s & 1) * 8 + (lane >> 2);
            rv1[rl * 2 + nh] = B1[s];
            rv2[rl * 2 + nh] = B2[s];
            ri1[rl * 2 + nh] = I1[s];
        }
    }
    __syncthreads();
    if (tid < 128) {
        float a1 = rv1[tid * 2], a2 = rv2[tid * 2];
        int ai = ri1[tid * 2];
        float o1 = rv1[tid * 2 + 1], o2 = rv2[tid * 2 + 1];
        int oi = ri1[tid * 2 + 1];
        float n2 = fminf(fminf(a2, o2), fmaxf(a1, o1));
        if (o1 < a1 || (o1 == a1 && oi < ai)) { a1 = o1; ai = oi; }
        g_b1[row0 + tid] = a1;
        g_b2[row0 + tid] = n2;
        g_i1[row0 + tid] = ai;
    }
}

// ---------------------------------------------------------------------------
// Kernel D0: compact gated rows into g_list; decided rows finalize directly.
// ---------------------------------------------------------------------------
__global__ __launch_bounds__(256) void compact_kernel() {
    int row = blockIdx.x * 256 + threadIdx.x;
    if (row >= NROWS) return;
    if (g_b2[row] - g_b1[row] >= GATE) {
        g_final[row] = g_i1[row];
    } else {
        int pos = atomicAdd(&g_count, 1);
        g_list[pos] = row;
    }
}

// ---------------------------------------------------------------------------
// Kernel D1: batched exact rescan. Block = (batch of 16 gated rows) x (1 of 8
// code splits). 256 threads, 4 codes each. x rows in smem (broadcast reads).
// ---------------------------------------------------------------------------
__global__ __launch_bounds__(256) void rescan_kernel(const float* __restrict__ cb) {
    const int batch = blockIdx.x >> 3;
    const int split = blockIdx.x & 7;
    const int base = batch * RS_ROWS;
    const int count = g_count;
    if (base >= count) return;
    const int nr = min(RS_ROWS, count - base);

    __shared__ float xs[RS_ROWS][DIM];
    __shared__ int   rowid[RS_ROWS];
    __shared__ float wv[8][RS_ROWS];
    __shared__ int   wi[8][RS_ROWS];

    const int tid = threadIdx.x;
    const int lane = tid & 31, warp = tid >> 5;

    if (tid < RS_ROWS) rowid[tid] = (tid < nr) ? g_list[base + tid] : g_list[base];
    __syncthreads();
    // load x rows: 16 rows x 32 float4 = 512 float4; 256 threads x 2
    #pragma unroll
    for (int i = 0; i < 2; i++) {
        int idx = i * 256 + tid;
        int r = idx >> 5, u = idx & 31;
        *(float4*)&xs[r][u * 4] = *(const float4*)&g_xn[(size_t)rowid[r] * DIM + u * 4];
    }
    __syncthreads();

    float bv[RS_ROWS];
    int   bi[RS_ROWS];
    #pragma unroll
    for (int r = 0; r < RS_ROWS; r++) { bv[r] = FLT_MAX; bi[r] = 0; }

    #pragma unroll
    for (int cc = 0; cc < 4; cc++) {
        int c = split * RS_CPS + cc * 256 + tid;
        const float4* cp = (const float4*)&cb[(size_t)c * DIM];
        float e2c = g_e2[c];
        float acc[RS_ROWS];
        #pragma unroll
        for (int r = 0; r < RS_ROWS; r++) acc[r] = 0.0f;
        #pragma unroll 8
        for (int d4 = 0; d4 < 32; d4++) {
            float4 cv = cp[d4];
            #pragma unroll
            for (int r = 0; r < RS_ROWS; r++) {
                float4 xv = *(const float4*)&xs[r][d4 * 4];
                acc[r] = fmaf(cv.x, xv.x, acc[r]);
                acc[r] = fmaf(cv.y, xv.y, acc[r]);
                acc[r] = fmaf(cv.z, xv.z, acc[r]);
                acc[r] = fmaf(cv.w, xv.w, acc[r]);
            }
        }
        #pragma unroll
        for (int r = 0; r < RS_ROWS; r++) {
            float dist = fmaf(-2.0f, acc[r], e2c);
            if (dist < bv[r] || (dist == bv[r] && c < bi[r])) { bv[r] = dist; bi[r] = c; }
        }
    }

    // warp reduce per row (lowest dist, then lowest idx)
    #pragma unroll
    for (int r = 0; r < RS_ROWS; r++) {
        #pragma unroll
        for (int off = 16; off > 0; off >>= 1) {
            float ov = __shfl_xor_sync(0xffffffffu, bv[r], off);
            int   oi = __shfl_xor_sync(0xffffffffu, bi[r], off);
            if (ov < bv[r] || (ov == bv[r] && oi < bi[r])) { bv[r] = ov; bi[r] = oi; }
        }
        if (lane == 0) { wv[warp][r] = bv[r]; wi[warp][r] = bi[r]; }
    }
    __syncthreads();
    if (tid < nr) {
        float v = wv[0][tid];
        int i = wi[0][tid];
        #pragma unroll
        for (int w = 1; w < 8; w++) {
            float ov = wv[w][tid];
            int oi = wi[w][tid];
            if (ov < v || (ov == v && oi < i)) { v = ov; i = oi; }
        }
        g_sv[(size_t)(base + tid) * RS_SPLITS + split] = v;
        g_si[(size_t)(base + tid) * RS_SPLITS + split] = i;
    }
}

// ---------------------------------------------------------------------------
// Kernel D2: combine splits per gated entry.
// ---------------------------------------------------------------------------
__global__ __launch_bounds__(256) void combine_kernel() {
    int e = blockIdx.x * 256 + threadIdx.x;
    if (e >= g_count) return;
    float v = g_sv[(size_t)e * RS_SPLITS];
    int i = g_si[(size_t)e * RS_SPLITS];
    #pragma unroll
    for (int s = 1; s < RS_SPLITS; s++) {
        float ov = g_sv[(size_t)e * RS_SPLITS + s];
        int oi = g_si[(size_t)e * RS_SPLITS + s];
        if (ov < v || (ov == v && oi < i)) { v = ov; i = oi; }
    }
    g_final[g_list[e]] = i;
}

// ---------------------------------------------------------------------------
// Kernel E: gather + per-block loss partials (deterministic).
// ---------------------------------------------------------------------------
__global__ __launch_bounds__(256) void gather_kernel(const float* __restrict__ cb,
                                                     float* __restrict__ out) {
    __shared__ float sw[8];
    int warp = threadIdx.x >> 5, lane = threadIdx.x & 31;
    int row = blockIdx.x * 8 + warp;
    int ind = g_final[row];
    float4 c = *(const float4*)&cb[(size_t)ind * DIM + lane * 4];
    float4 xv = *(const float4*)&g_xn[(size_t)row * DIM + lane * 4];
    *(float4*)&out[OUT_Q + (size_t)row * DIM + lane * 4] = c;
    float dx = c.x - xv.x, dy = c.y - xv.y, dz = c.z - xv.z, dw = c.w - xv.w;
    float s = dx * dx + dy * dy + dz * dz + dw * dw;
    #pragma unroll
    for (int o = 16; o > 0; o >>= 1) s += __shfl_xor_sync(0xffffffffu, s, o);
    if (lane == 0) { out[OUT_IND + row] = (float)ind; sw[warp] = s; }
    __syncthreads();
    if (threadIdx.x == 0) {
        float tot = 0.0f;
        #pragma unroll
        for (int w = 0; w < 8; w++) tot += sw[w];
        g_part[blockIdx.x] = tot;
    }
}

__global__ __launch_bounds__(256) void final_kernel(float* __restrict__ out) {
    __shared__ float sp[256];
    int tid = threadIdx.x;
    float s = 0.0f;
    for (int i = tid; i < GATHER_BLOCKS; i += 256) s += g_part[i];
    sp[tid] = s;
    __syncthreads();
    for (int o = 128; o > 0; o >>= 1) {
        if (tid < o) sp[tid] += sp[tid + o];
        __syncthreads();
    }
    if (tid == 0) out[OUT_LOSS] = sp[0] * (1.0f / (float)(NROWS * DIM));
}

// ---------------------------------------------------------------------------
extern "C" void kernel_launch(void* const* d_in, const int* in_sizes, int n_in,
                              void* d_out, int out_size) {
    const float* x = (const float*)d_in[0];
    const float* cb = (const float*)d_in[1];
    float* out = (float*)d_out;

    cudaFuncSetAttribute(nn_kernel, cudaFuncAttributeMaxDynamicSharedMemorySize,
                         NN_SMEM);

    ln_kernel<<<NROWS / 8, 256>>>(x);
    cb_kernel<<<KCODES / 8, 256>>>(cb);
    nn_kernel<<<NN_CTAS, 256, NN_SMEM>>>();
    compact_kernel<<<NROWS / 256, 256>>>();
    rescan_kernel<<<RS_GRID, 256>>>(cb);
    combine_kernel<<<NROWS / 256, 256>>>();
    gather_kernel<<<GATHER_BLOCKS, 256>>>(cb, out);
    final_kernel<<<1, 256>>>(out);
}

// round 5
// speedup vs baseline: 2.2106x; 1.2644x over previous
#include <cuda_runtime.h>
#include <cuda_fp16.h>
#include <cstdint>
#include <cfloat>

// ---------------------------------------------------------------- constants
#define NROWS  16384
#define DIM    128
#define KCODES 8192
#define NN_CTAS 128          // 128 row-tiles of 128
#define NTILE   64           // 64 code-tiles of 128
#define GATE    0.05f

#define OUT_Q    0
#define OUT_IND  (NROWS * DIM)
#define OUT_LOSS (NROWS * DIM + NROWS)
#define GATHER_BLOCKS (NROWS / 8)

// rescan config
#define RS_ROWS   16
#define RS_SPLITS 8
#define RS_CPS    (KCODES / RS_SPLITS)    // 1024 codes per split
#define RS_MAXBATCH (NROWS / RS_ROWS)     // 1024
#define RS_GRID   (RS_MAXBATCH * RS_SPLITS)

// smem layout. Rows padded: 128 fp16 = 256B data + 16B pad = 272B.
#define ROWB    272
#define BLKB    (128 * ROWB)          // 34816 bytes per [128 x 128fp16] block
#define A_OFF   0                     // 2 blocks (hi, lo) = 69632
#define B_OFF   (2 * BLKB)            // 2 buffers x 1 block = 69632
#define E2_OFF  (B_OFF + 2 * BLKB)    // 2 x 512B
#define NN_SMEM (E2_OFF + 1024)       // 140288

// ------------------------------------------------------------- device scratch
__device__ __half g_Ahi[NROWS * DIM];
__device__ __half g_Alo[NROWS * DIM];
__device__ __half g_Bh[KCODES * DIM];
__device__ float g_xn[NROWS * DIM];
__device__ float g_e2[KCODES];
__device__ float g_b1[NROWS];
__device__ float g_b2[NROWS];
__device__ int   g_i1[NROWS];
__device__ int   g_final[NROWS];
__device__ float g_part[GATHER_BLOCKS];
__device__ int   g_count;
__device__ int   g_list[NROWS];
__device__ float g_sv[NROWS * RS_SPLITS];
__device__ int   g_si[NROWS * RS_SPLITS];

// ------------------------------------------------------------- PTX helpers
__device__ __forceinline__ uint32_t smem_to_u32(const void* p) {
    uint32_t a;
    asm("{ .reg .u64 t; cvta.to.shared.u64 t, %1; cvt.u32.u64 %0, t; }"
        : "=r"(a) : "l"(p));
    return a;
}
#define CP_ASYNC16(dst, src) \
    asm volatile("cp.async.cg.shared.global [%0], [%1], 16;" \
                 :: "r"(dst), "l"(src) : "memory")
#define CP_COMMIT() asm volatile("cp.async.commit_group;" ::: "memory")
#define CP_WAIT0()  asm volatile("cp.async.wait_group 0;" ::: "memory")

#define LDSM_X4(r0, r1, r2, r3, addr) \
    asm volatile("ldmatrix.sync.aligned.m8n8.x4.shared.b16 {%0,%1,%2,%3}, [%4];" \
                 : "=r"(r0), "=r"(r1), "=r"(r2), "=r"(r3) : "r"(addr))

__device__ __forceinline__ void mma16816(float* c, const uint32_t* a,
                                         uint32_t b0, uint32_t b1) {
    asm volatile(
        "mma.sync.aligned.m16n8k16.row.col.f32.f16.f16.f32 "
        "{%0,%1,%2,%3}, {%4,%5,%6,%7}, {%8,%9}, {%0,%1,%2,%3};"
        : "+f"(c[0]), "+f"(c[1]), "+f"(c[2]), "+f"(c[3])
        : "r"(a[0]), "r"(a[1]), "r"(a[2]), "r"(a[3]), "r"(b0), "r"(b1));
}

// ---------------------------------------------------------------------------
// Kernel A: layernorm -> g_xn (f32) + hi/lo fp16 split. 1 row per warp.
// ---------------------------------------------------------------------------
__global__ __launch_bounds__(256) void ln_kernel(const float* __restrict__ x) {
    if (blockIdx.x == 0 && threadIdx.x == 0) g_count = 0;
    int warp = threadIdx.x >> 5, lane = threadIdx.x & 31;
    int row = blockIdx.x * 8 + warp;
    float4 v = *(const float4*)&x[(size_t)row * DIM + lane * 4];
    float s = v.x + v.y + v.z + v.w;
    #pragma unroll
    for (int o = 16; o > 0; o >>= 1) s += __shfl_xor_sync(0xffffffffu, s, o);
    float mu = s * (1.0f / 128.0f);
    float dx = v.x - mu, dy = v.y - mu, dz = v.z - mu, dw = v.w - mu;
    float q = dx * dx + dy * dy + dz * dz + dw * dw;
    #pragma unroll
    for (int o = 16; o > 0; o >>= 1) q += __shfl_xor_sync(0xffffffffu, q, o);
    float rs = rsqrtf(q * (1.0f / 128.0f) + 1e-5f);
    float y[4] = {dx * rs, dy * rs, dz * rs, dw * rs};
    *(float4*)&g_xn[(size_t)row * DIM + lane * 4] = make_float4(y[0], y[1], y[2], y[3]);
    __half h[4], l[4];
    #pragma unroll
    for (int i = 0; i < 4; i++) {
        h[i] = __float2half(y[i]);
        l[i] = __float2half(y[i] - __half2float(h[i]));
    }
    *(uint2*)&g_Ahi[(size_t)row * DIM + lane * 4] = *(uint2*)h;
    *(uint2*)&g_Alo[(size_t)row * DIM + lane * 4] = *(uint2*)l;
}

// ---------------------------------------------------------------------------
// Kernel B: codebook -> e2 (exact f32) + fp16 hi. 1 code per warp.
// ---------------------------------------------------------------------------
__global__ __launch_bounds__(256) void cb_kernel(const float* __restrict__ cb) {
    int warp = threadIdx.x >> 5, lane = threadIdx.x & 31;
    int row = blockIdx.x * 8 + warp;
    float4 v = *(const float4*)&cb[(size_t)row * DIM + lane * 4];
    float q = v.x * v.x + v.y * v.y + v.z * v.z + v.w * v.w;
    #pragma unroll
    for (int o = 16; o > 0; o >>= 1) q += __shfl_xor_sync(0xffffffffu, q, o);
    if (lane == 0) g_e2[row] = q;
    __half h[4] = {__float2half(v.x), __float2half(v.y),
                   __float2half(v.z), __float2half(v.w)};
    *(uint2*)&g_Bh[(size_t)row * DIM + lane * 4] = *(uint2*)h;
}

// ---------------------------------------------------------------------------
// Kernel C: HMMA fp16 2-term distance GEMM + per-row top-2.
// 128 CTAs x 256 thr. CTA: 128 rows x 8192 codes (64 tiles), K=256 (hi|lo vs B).
// ---------------------------------------------------------------------------
__global__ __launch_bounds__(256, 1) void nn_kernel() {
    extern __shared__ char sptr[];
    const uint32_t sbase = smem_to_u32(sptr);
    const int tid = threadIdx.x;
    const int lane = tid & 31;
    const int w = tid >> 5;
    const int mrow = (w & 3) * 32;
    const int ncol0 = (w >> 2) * 64;
    const int row0 = blockIdx.x * 128;

    // A tile (once): 2 blocks (hi, lo)
    #pragma unroll
    for (int i = 0; i < 16; i++) {
        int idx = i * 256 + tid;
        int kb = idx >> 11;
        int r = (idx >> 4) & 127;
        int u = idx & 15;
        const __half* src =
            (kb ? g_Alo : g_Ahi) + (size_t)(row0 + r) * DIM + u * 8;
        uint4 v = *(const uint4*)src;
        *(uint4*)(sptr + A_OFF + kb * BLKB + r * ROWB + u * 16) = v;
    }
    // B tile 0 (1 block) + e2 slot 0
    {
        uint32_t bb = sbase + B_OFF;
        #pragma unroll
        for (int i = 0; i < 8; i++) {
            int idx = i * 256 + tid;
            int r = (idx >> 4) & 127;
            int u = idx & 15;
            CP_ASYNC16(bb + r * ROWB + u * 16, g_Bh + (size_t)r * DIM + u * 8);
        }
        if (tid < 32) CP_ASYNC16(sbase + E2_OFF + tid * 16, (const char*)g_e2 + tid * 16);
        CP_COMMIT();
    }

    float B1[4], B2[4];
    int I1[4];
    #pragma unroll
    for (int s = 0; s < 4; s++) { B1[s] = FLT_MAX; B2[s] = FLT_MAX; I1[s] = 0; }

    const uint32_t a_row = mrow + (lane & 15);
    const uint32_t a_cb = (lane >> 4) << 4;
    const uint32_t b_row = ncol0 + (lane & 7) + ((lane & 16) >> 1);
    const uint32_t b_k8 = (lane & 8);

    for (int t = 0; t < NTILE; t++) {
        CP_WAIT0();
        __syncthreads();
        if (t + 1 < NTILE) {
            uint32_t bb = sbase + B_OFF + ((t + 1) & 1) * BLKB;
            const size_t crow0 = (size_t)(t + 1) * 128;
            #pragma unroll
            for (int i = 0; i < 8; i++) {
                int idx = i * 256 + tid;
                int r = (idx >> 4) & 127;
                int u = idx & 15;
                CP_ASYNC16(bb + r * ROWB + u * 16, g_Bh + (crow0 + r) * DIM + u * 8);
            }
            if (tid < 32)
                CP_ASYNC16(sbase + E2_OFF + ((t + 1) & 1) * 512 + tid * 16,
                           (const char*)(g_e2 + (t + 1) * 128) + tid * 16);
            CP_COMMIT();
        }

        const uint32_t bufB = sbase + B_OFF + (t & 1) * BLKB;
        float c[2][8][4];
        #pragma unroll
        for (int mb = 0; mb < 2; mb++)
            #pragma unroll
            for (int nb = 0; nb < 8; nb++)
                #pragma unroll
                for (int q = 0; q < 4; q++) c[mb][nb][q] = 0.0f;

        #pragma unroll
        for (int j = 0; j < 16; j++) {
            const int asel = j >> 3;                 // lo-A for last 8 steps
            const int kk = (j & 7) * 16;
            uint32_t a[2][4];
            #pragma unroll
            for (int mb = 0; mb < 2; mb++) {
                uint32_t addr = sbase + A_OFF + asel * BLKB +
                                (a_row + mb * 16) * ROWB + kk * 2 + a_cb;
                LDSM_X4(a[mb][0], a[mb][1], a[mb][2], a[mb][3], addr);
            }
            uint32_t b[4][4];
            #pragma unroll
            for (int nb4 = 0; nb4 < 4; nb4++) {
                uint32_t addr = bufB +
                                (b_row + nb4 * 16) * ROWB + (kk + b_k8) * 2;
                LDSM_X4(b[nb4][0], b[nb4][1], b[nb4][2], b[nb4][3], addr);
            }
            #pragma unroll
            for (int mb = 0; mb < 2; mb++)
                #pragma unroll
                for (int nb = 0; nb < 8; nb++)
                    mma16816(c[mb][nb], a[mb],
                             b[nb >> 1][(nb & 1) * 2], b[nb >> 1][(nb & 1) * 2 + 1]);
        }

        const float* e2p = (const float*)(sptr + E2_OFF + (t & 1) * 512);
        const int colb = ncol0 + 2 * (lane & 3);
        #pragma unroll
        for (int nb = 0; nb < 8; nb++) {
            float2 ev = *(const float2*)&e2p[colb + nb * 8];
            int gidx = t * 128 + colb + nb * 8;
            #pragma unroll
            for (int mb = 0; mb < 2; mb++)
                #pragma unroll
                for (int hi = 0; hi < 2; hi++) {
                    int s = mb * 2 + hi;
                    float d0 = fmaf(-2.0f, c[mb][nb][hi * 2 + 0], ev.x);
                    float d1 = fmaf(-2.0f, c[mb][nb][hi * 2 + 1], ev.y);
                    if (d0 < B1[s]) { B2[s] = B1[s]; B1[s] = d0; I1[s] = gidx; }
                    else if (d0 < B2[s]) { B2[s] = d0; }
                    if (d1 < B1[s]) { B2[s] = B1[s]; B1[s] = d1; I1[s] = gidx + 1; }
                    else if (d1 < B2[s]) { B2[s] = d1; }
                }
        }
    }

    #pragma unroll
    for (int s = 0; s < 4; s++) {
        #pragma unroll
        for (int off = 1; off < 4; off <<= 1) {
            float ob1 = __shfl_xor_sync(0xffffffffu, B1[s], off);
            float ob2 = __shfl_xor_sync(0xffffffffu, B2[s], off);
            int oi1 = __shfl_xor_sync(0xffffffffu, I1[s], off);
            float nb2 = fminf(fminf(B2[s], ob2), fmaxf(B1[s], ob1));
            if (ob1 < B1[s] || (ob1 == B1[s] && oi1 < I1[s])) { B1[s] = ob1; I1[s] = oi1; }
            B2[s] = nb2;
        }
    }
    __syncthreads();
    float* rv1 = (float*)sptr;
    float* rv2 = rv1 + 256;
    int*   ri1 = (int*)(rv2 + 256);
    if ((lane & 3) == 0) {
        int nh = w >> 2;
        #pragma unroll
        for (int s = 0; s < 4; s++) {
            int rl = mrow + (s >> 1) * 16 + (s & 1) * 8 + (lane >> 2);
            rv1[rl * 2 + nh] = B1[s];
            rv2[rl * 2 + nh] = B2[s];
            ri1[rl * 2 + nh] = I1[s];
        }
    }
    __syncthreads();
    if (tid < 128) {
        float a1 = rv1[tid * 2], a2 = rv2[tid * 2];
        int ai = ri1[tid * 2];
        float o1 = rv1[tid * 2 + 1], o2 = rv2[tid * 2 + 1];
        int oi = ri1[tid * 2 + 1];
        float n2 = fminf(fminf(a2, o2), fmaxf(a1, o1));
        if (o1 < a1 || (o1 == a1 && oi < ai)) { a1 = o1; ai = oi; }
        g_b1[row0 + tid] = a1;
        g_b2[row0 + tid] = n2;
        g_i1[row0 + tid] = ai;
    }
}

// ---------------------------------------------------------------------------
// Kernel D0: compact gated rows into g_list; decided rows finalize directly.
// ---------------------------------------------------------------------------
__global__ __launch_bounds__(256) void compact_kernel() {
    int row = blockIdx.x * 256 + threadIdx.x;
    if (row >= NROWS) return;
    if (g_b2[row] - g_b1[row] >= GATE) {
        g_final[row] = g_i1[row];
    } else {
        int pos = atomicAdd(&g_count, 1);
        g_list[pos] = row;
    }
}

// ---------------------------------------------------------------------------
// Kernel D1: batched exact rescan (16 gated rows x 1/8 code split per block).
// ---------------------------------------------------------------------------
__global__ __launch_bounds__(256) void rescan_kernel(const float* __restrict__ cb) {
    const int batch = blockIdx.x >> 3;
    const int split = blockIdx.x & 7;
    const int base = batch * RS_ROWS;
    const int count = g_count;
    if (base >= count) return;
    const int nr = min(RS_ROWS, count - base);

    __shared__ float xs[RS_ROWS][DIM];
    __shared__ int   rowid[RS_ROWS];
    __shared__ float wv[8][RS_ROWS];
    __shared__ int   wi[8][RS_ROWS];

    const int tid = threadIdx.x;
    const int lane = tid & 31, warp = tid >> 5;

    if (tid < RS_ROWS) rowid[tid] = (tid < nr) ? g_list[base + tid] : g_list[base];
    __syncthreads();
    #pragma unroll
    for (int i = 0; i < 2; i++) {
        int idx = i * 256 + tid;
        int r = idx >> 5, u = idx & 31;
        *(float4*)&xs[r][u * 4] = *(const float4*)&g_xn[(size_t)rowid[r] * DIM + u * 4];
    }
    __syncthreads();

    float bv[RS_ROWS];
    int   bi[RS_ROWS];
    #pragma unroll
    for (int r = 0; r < RS_ROWS; r++) { bv[r] = FLT_MAX; bi[r] = 0; }

    #pragma unroll
    for (int cc = 0; cc < 4; cc++) {
        int c = split * RS_CPS + cc * 256 + tid;
        const float4* cp = (const float4*)&cb[(size_t)c * DIM];
        float e2c = g_e2[c];
        float acc[RS_ROWS];
        #pragma unroll
        for (int r = 0; r < RS_ROWS; r++) acc[r] = 0.0f;
        #pragma unroll 8
        for (int d4 = 0; d4 < 32; d4++) {
            float4 cv = cp[d4];
            #pragma unroll
            for (int r = 0; r < RS_ROWS; r++) {
                float4 xv = *(const float4*)&xs[r][d4 * 4];
                acc[r] = fmaf(cv.x, xv.x, acc[r]);
                acc[r] = fmaf(cv.y, xv.y, acc[r]);
                acc[r] = fmaf(cv.z, xv.z, acc[r]);
                acc[r] = fmaf(cv.w, xv.w, acc[r]);
            }
        }
        #pragma unroll
        for (int r = 0; r < RS_ROWS; r++) {
            float dist = fmaf(-2.0f, acc[r], e2c);
            if (dist < bv[r] || (dist == bv[r] && c < bi[r])) { bv[r] = dist; bi[r] = c; }
        }
    }

    #pragma unroll
    for (int r = 0; r < RS_ROWS; r++) {
        #pragma unroll
        for (int off = 16; off > 0; off >>= 1) {
            float ov = __shfl_xor_sync(0xffffffffu, bv[r], off);
            int   oi = __shfl_xor_sync(0xffffffffu, bi[r], off);
            if (ov < bv[r] || (ov == bv[r] && oi < bi[r])) { bv[r] = ov; bi[r] = oi; }
        }
        if (lane == 0) { wv[warp][r] = bv[r]; wi[warp][r] = bi[r]; }
    }
    __syncthreads();
    if (tid < nr) {
        float v = wv[0][tid];
        int i = wi[0][tid];
        #pragma unroll
        for (int w = 1; w < 8; w++) {
            float ov = wv[w][tid];
            int oi = wi[w][tid];
            if (ov < v || (ov == v && oi < i)) { v = ov; i = oi; }
        }
        g_sv[(size_t)(base + tid) * RS_SPLITS + split] = v;
        g_si[(size_t)(base + tid) * RS_SPLITS + split] = i;
    }
}

// ---------------------------------------------------------------------------
// Kernel D2: combine splits per gated entry.
// ---------------------------------------------------------------------------
__global__ __launch_bounds__(256) void combine_kernel() {
    int e = blockIdx.x * 256 + threadIdx.x;
    if (e >= g_count) return;
    float v = g_sv[(size_t)e * RS_SPLITS];
    int i = g_si[(size_t)e * RS_SPLITS];
    #pragma unroll
    for (int s = 1; s < RS_SPLITS; s++) {
        float ov = g_sv[(size_t)e * RS_SPLITS + s];
        int oi = g_si[(size_t)e * RS_SPLITS + s];
        if (ov < v || (ov == v && oi < i)) { v = ov; i = oi; }
    }
    g_final[g_list[e]] = i;
}

// ---------------------------------------------------------------------------
// Kernel E: gather + per-block loss partials (deterministic).
// ---------------------------------------------------------------------------
__global__ __launch_bounds__(256) void gather_kernel(const float* __restrict__ cb,
                                                     float* __restrict__ out) {
    __shared__ float sw[8];
    int warp = threadIdx.x >> 5, lane = threadIdx.x & 31;
    int row = blockIdx.x * 8 + warp;
    int ind = g_final[row];
    float4 c = *(const float4*)&cb[(size_t)ind * DIM + lane * 4];
    float4 xv = *(const float4*)&g_xn[(size_t)row * DIM + lane * 4];
    *(float4*)&out[OUT_Q + (size_t)row * DIM + lane * 4] = c;
    float dx = c.x - xv.x, dy = c.y - xv.y, dz = c.z - xv.z, dw = c.w - xv.w;
    float s = dx * dx + dy * dy + dz * dz + dw * dw;
    #pragma unroll
    for (int o = 16; o > 0; o >>= 1) s += __shfl_xor_sync(0xffffffffu, s, o);
    if (lane == 0) { out[OUT_IND + row] = (float)ind; sw[warp] = s; }
    __syncthreads();
    if (threadIdx.x == 0) {
        float tot = 0.0f;
        #pragma unroll
        for (int w = 0; w < 8; w++) tot += sw[w];
        g_part[blockIdx.x] = tot;
    }
}

__global__ __launch_bounds__(256) void final_kernel(float* __restrict__ out) {
    __shared__ float sp[256];
    int tid = threadIdx.x;
    float s = 0.0f;
    for (int i = tid; i < GATHER_BLOCKS; i += 256) s += g_part[i];
    sp[tid] = s;
    __syncthreads();
    for (int o = 128; o > 0; o >>= 1) {
        if (tid < o) sp[tid] += sp[tid + o];
        __syncthreads();
    }
    if (tid == 0) out[OUT_LOSS] = sp[0] * (1.0f / (float)(NROWS * DIM));
}

// ---------------------------------------------------------------------------
extern "C" void kernel_launch(void* const* d_in, const int* in_sizes, int n_in,
                              void* d_out, int out_size) {
    const float* x = (const float*)d_in[0];
    const float* cb = (const float*)d_in[1];
    float* out = (float*)d_out;

    cudaFuncSetAttribute(nn_kernel, cudaFuncAttributeMaxDynamicSharedMemorySize,
                         NN_SMEM);

    ln_kernel<<<NROWS / 8, 256>>>(x);
    cb_kernel<<<KCODES / 8, 256>>>(cb);
    nn_kernel<<<NN_CTAS, 256, NN_SMEM>>>();
    compact_kernel<<<NROWS / 256, 256>>>();
    rescan_kernel<<<RS_GRID, 256>>>(cb);
    combine_kernel<<<NROWS / 256, 256>>>();
    gather_kernel<<<GATHER_BLOCKS, 256>>>(cb, out);
    final_kernel<<<1, 256>>>(out);
}

// round 6
// speedup vs baseline: 2.3320x; 1.0549x over previous
#include <cuda_runtime.h>
#include <cuda_fp16.h>
#include <cstdint>
#include <cfloat>

// ---------------------------------------------------------------- constants
#define NROWS  16384
#define DIM    128
#define KCODES 8192
#define NN_CTAS 128          // 128 row-tiles of 128
#define NTILE   64           // 64 code-tiles of 128
#define GATE    0.05f

#define OUT_Q    0
#define OUT_IND  (NROWS * DIM)
#define OUT_LOSS (NROWS * DIM + NROWS)
#define GATHER_BLOCKS (NROWS / 8)

// smem layout. Rows padded: 128 fp16 = 256B data + 16B pad = 272B.
#define ROWB    272
#define BLKB    (128 * ROWB)          // 34816 bytes per [128 x 128fp16] block
#define A_OFF   0                     // 2 blocks (hi, lo) = 69632
#define B_OFF   (2 * BLKB)            // 2 buffers x 1 block = 69632
#define E2_OFF  (B_OFF + 2 * BLKB)    // 2 x 512B
#define NN_SMEM (E2_OFF + 1024)       // 140288

// ------------------------------------------------------------- device scratch
__device__ __half g_Ahi[NROWS * DIM];
__device__ __half g_Alo[NROWS * DIM];
__device__ __half g_Bh[KCODES * DIM];
__device__ float g_xn[NROWS * DIM];
__device__ float g_e2[KCODES];
__device__ float g_b1[NROWS];
__device__ float g_b2[NROWS];
__device__ int   g_i1[NROWS];
__device__ int   g_final[NROWS];
__device__ float g_part[GATHER_BLOCKS];
__device__ int   g_count;
__device__ int   g_list[NROWS];
__device__ float g_tmin[(size_t)NROWS * 128];   // per-row, per-(tile,half) approx min

// ------------------------------------------------------------- PTX helpers
__device__ __forceinline__ uint32_t smem_to_u32(const void* p) {
    uint32_t a;
    asm("{ .reg .u64 t; cvta.to.shared.u64 t, %1; cvt.u32.u64 %0, t; }"
        : "=r"(a) : "l"(p));
    return a;
}
#define CP_ASYNC16(dst, src) \
    asm volatile("cp.async.cg.shared.global [%0], [%1], 16;" \
                 :: "r"(dst), "l"(src) : "memory")
#define CP_COMMIT() asm volatile("cp.async.commit_group;" ::: "memory")
#define CP_WAIT0()  asm volatile("cp.async.wait_group 0;" ::: "memory")

#define LDSM_X4(r0, r1, r2, r3, addr) \
    asm volatile("ldmatrix.sync.aligned.m8n8.x4.shared.b16 {%0,%1,%2,%3}, [%4];" \
                 : "=r"(r0), "=r"(r1), "=r"(r2), "=r"(r3) : "r"(addr))

__device__ __forceinline__ void mma16816(float* c, const uint32_t* a,
                                         uint32_t b0, uint32_t b1) {
    asm volatile(
        "mma.sync.aligned.m16n8k16.row.col.f32.f16.f16.f32 "
        "{%0,%1,%2,%3}, {%4,%5,%6,%7}, {%8,%9}, {%0,%1,%2,%3};"
        : "+f"(c[0]), "+f"(c[1]), "+f"(c[2]), "+f"(c[3])
        : "r"(a[0]), "r"(a[1]), "r"(a[2]), "r"(a[3]), "r"(b0), "r"(b1));
}

// ---------------------------------------------------------------------------
// Kernel A: layernorm -> g_xn (f32) + hi/lo fp16 split. 1 row per warp.
// ---------------------------------------------------------------------------
__global__ __launch_bounds__(256) void ln_kernel(const float* __restrict__ x) {
    if (blockIdx.x == 0 && threadIdx.x == 0) g_count = 0;
    int warp = threadIdx.x >> 5, lane = threadIdx.x & 31;
    int row = blockIdx.x * 8 + warp;
    float4 v = *(const float4*)&x[(size_t)row * DIM + lane * 4];
    float s = v.x + v.y + v.z + v.w;
    #pragma unroll
    for (int o = 16; o > 0; o >>= 1) s += __shfl_xor_sync(0xffffffffu, s, o);
    float mu = s * (1.0f / 128.0f);
    float dx = v.x - mu, dy = v.y - mu, dz = v.z - mu, dw = v.w - mu;
    float q = dx * dx + dy * dy + dz * dz + dw * dw;
    #pragma unroll
    for (int o = 16; o > 0; o >>= 1) q += __shfl_xor_sync(0xffffffffu, q, o);
    float rs = rsqrtf(q * (1.0f / 128.0f) + 1e-5f);
    float y[4] = {dx * rs, dy * rs, dz * rs, dw * rs};
    *(float4*)&g_xn[(size_t)row * DIM + lane * 4] = make_float4(y[0], y[1], y[2], y[3]);
    __half h[4], l[4];
    #pragma unroll
    for (int i = 0; i < 4; i++) {
        h[i] = __float2half(y[i]);
        l[i] = __float2half(y[i] - __half2float(h[i]));
    }
    *(uint2*)&g_Ahi[(size_t)row * DIM + lane * 4] = *(uint2*)h;
    *(uint2*)&g_Alo[(size_t)row * DIM + lane * 4] = *(uint2*)l;
}

// ---------------------------------------------------------------------------
// Kernel B: codebook -> e2 (exact f32) + fp16 hi. 1 code per warp.
// ---------------------------------------------------------------------------
__global__ __launch_bounds__(256) void cb_kernel(const float* __restrict__ cb) {
    int warp = threadIdx.x >> 5, lane = threadIdx.x & 31;
    int row = blockIdx.x * 8 + warp;
    float4 v = *(const float4*)&cb[(size_t)row * DIM + lane * 4];
    float q = v.x * v.x + v.y * v.y + v.z * v.z + v.w * v.w;
    #pragma unroll
    for (int o = 16; o > 0; o >>= 1) q += __shfl_xor_sync(0xffffffffu, q, o);
    if (lane == 0) g_e2[row] = q;
    __half h[4] = {__float2half(v.x), __float2half(v.y),
                   __float2half(v.z), __float2half(v.w)};
    *(uint2*)&g_Bh[(size_t)row * DIM + lane * 4] = *(uint2*)h;
}

// ---------------------------------------------------------------------------
// Kernel C: HMMA fp16 2-term distance GEMM + per-row top-2 + per-half-tile min.
// ---------------------------------------------------------------------------
__global__ __launch_bounds__(256, 1) void nn_kernel() {
    extern __shared__ char sptr[];
    const uint32_t sbase = smem_to_u32(sptr);
    const int tid = threadIdx.x;
    const int lane = tid & 31;
    const int w = tid >> 5;
    const int mrow = (w & 3) * 32;
    const int ncol0 = (w >> 2) * 64;
    const int row0 = blockIdx.x * 128;

    // A tile (once): 2 blocks (hi, lo)
    #pragma unroll
    for (int i = 0; i < 16; i++) {
        int idx = i * 256 + tid;
        int kb = idx >> 11;
        int r = (idx >> 4) & 127;
        int u = idx & 15;
        const __half* src =
            (kb ? g_Alo : g_Ahi) + (size_t)(row0 + r) * DIM + u * 8;
        uint4 v = *(const uint4*)src;
        *(uint4*)(sptr + A_OFF + kb * BLKB + r * ROWB + u * 16) = v;
    }
    // B tile 0 (1 block) + e2 slot 0
    {
        uint32_t bb = sbase + B_OFF;
        #pragma unroll
        for (int i = 0; i < 8; i++) {
            int idx = i * 256 + tid;
            int r = (idx >> 4) & 127;
            int u = idx & 15;
            CP_ASYNC16(bb + r * ROWB + u * 16, g_Bh + (size_t)r * DIM + u * 8);
        }
        if (tid < 32) CP_ASYNC16(sbase + E2_OFF + tid * 16, (const char*)g_e2 + tid * 16);
        CP_COMMIT();
    }

    float B1[4], B2[4];
    int I1[4];
    #pragma unroll
    for (int s = 0; s < 4; s++) { B1[s] = FLT_MAX; B2[s] = FLT_MAX; I1[s] = 0; }

    const uint32_t a_row = mrow + (lane & 15);
    const uint32_t a_cb = (lane >> 4) << 4;
    const uint32_t b_row = ncol0 + (lane & 7) + ((lane & 16) >> 1);
    const uint32_t b_k8 = (lane & 8);

    for (int t = 0; t < NTILE; t++) {
        CP_WAIT0();
        __syncthreads();
        if (t + 1 < NTILE) {
            uint32_t bb = sbase + B_OFF + ((t + 1) & 1) * BLKB;
            const size_t crow0 = (size_t)(t + 1) * 128;
            #pragma unroll
            for (int i = 0; i < 8; i++) {
                int idx = i * 256 + tid;
                int r = (idx >> 4) & 127;
                int u = idx & 15;
                CP_ASYNC16(bb + r * ROWB + u * 16, g_Bh + (crow0 + r) * DIM + u * 8);
            }
            if (tid < 32)
                CP_ASYNC16(sbase + E2_OFF + ((t + 1) & 1) * 512 + tid * 16,
                           (const char*)(g_e2 + (t + 1) * 128) + tid * 16);
            CP_COMMIT();
        }

        const uint32_t bufB = sbase + B_OFF + (t & 1) * BLKB;
        float c[2][8][4];
        #pragma unroll
        for (int mb = 0; mb < 2; mb++)
            #pragma unroll
            for (int nb = 0; nb < 8; nb++)
                #pragma unroll
                for (int q = 0; q < 4; q++) c[mb][nb][q] = 0.0f;

        #pragma unroll
        for (int j = 0; j < 16; j++) {
            const int asel = j >> 3;                 // lo-A for last 8 steps
            const int kk = (j & 7) * 16;
            uint32_t a[2][4];
            #pragma unroll
            for (int mb = 0; mb < 2; mb++) {
                uint32_t addr = sbase + A_OFF + asel * BLKB +
                                (a_row + mb * 16) * ROWB + kk * 2 + a_cb;
                LDSM_X4(a[mb][0], a[mb][1], a[mb][2], a[mb][3], addr);
            }
            uint32_t b[4][4];
            #pragma unroll
            for (int nb4 = 0; nb4 < 4; nb4++) {
                uint32_t addr = bufB +
                                (b_row + nb4 * 16) * ROWB + (kk + b_k8) * 2;
                LDSM_X4(b[nb4][0], b[nb4][1], b[nb4][2], b[nb4][3], addr);
            }
            #pragma unroll
            for (int mb = 0; mb < 2; mb++)
                #pragma unroll
                for (int nb = 0; nb < 8; nb++)
                    mma16816(c[mb][nb], a[mb],
                             b[nb >> 1][(nb & 1) * 2], b[nb >> 1][(nb & 1) * 2 + 1]);
        }

        const float* e2p = (const float*)(sptr + E2_OFF + (t & 1) * 512);
        const int colb = ncol0 + 2 * (lane & 3);
        float tm[4] = {FLT_MAX, FLT_MAX, FLT_MAX, FLT_MAX};
        #pragma unroll
        for (int nb = 0; nb < 8; nb++) {
            float2 ev = *(const float2*)&e2p[colb + nb * 8];
            int gidx = t * 128 + colb + nb * 8;
            #pragma unroll
            for (int mb = 0; mb < 2; mb++)
                #pragma unroll
                for (int hi = 0; hi < 2; hi++) {
                    int s = mb * 2 + hi;
                    float d0 = fmaf(-2.0f, c[mb][nb][hi * 2 + 0], ev.x);
                    float d1 = fmaf(-2.0f, c[mb][nb][hi * 2 + 1], ev.y);
                    tm[s] = fminf(tm[s], fminf(d0, d1));
                    if (d0 < B1[s]) { B2[s] = B1[s]; B1[s] = d0; I1[s] = gidx; }
                    else if (d0 < B2[s]) { B2[s] = d0; }
                    if (d1 < B1[s]) { B2[s] = B1[s]; B1[s] = d1; I1[s] = gidx + 1; }
                    else if (d1 < B2[s]) { B2[s] = d1; }
                }
        }
        // per-(row, tile, warp-half) approx min -> gmem
        #pragma unroll
        for (int s = 0; s < 4; s++) {
            float m = tm[s];
            m = fminf(m, __shfl_xor_sync(0xffffffffu, m, 1));
            m = fminf(m, __shfl_xor_sync(0xffffffffu, m, 2));
            if ((lane & 3) == 0) {
                int rl = mrow + (s >> 1) * 16 + (s & 1) * 8 + (lane >> 2);
                g_tmin[(size_t)(row0 + rl) * 128 + t * 2 + (w >> 2)] = m;
            }
        }
    }

    #pragma unroll
    for (int s = 0; s < 4; s++) {
        #pragma unroll
        for (int off = 1; off < 4; off <<= 1) {
            float ob1 = __shfl_xor_sync(0xffffffffu, B1[s], off);
            float ob2 = __shfl_xor_sync(0xffffffffu, B2[s], off);
            int oi1 = __shfl_xor_sync(0xffffffffu, I1[s], off);
            float nb2 = fminf(fminf(B2[s], ob2), fmaxf(B1[s], ob1));
            if (ob1 < B1[s] || (ob1 == B1[s] && oi1 < I1[s])) { B1[s] = ob1; I1[s] = oi1; }
            B2[s] = nb2;
        }
    }
    __syncthreads();
    float* rv1 = (float*)sptr;
    float* rv2 = rv1 + 256;
    int*   ri1 = (int*)(rv2 + 256);
    if ((lane & 3) == 0) {
        int nh = w >> 2;
        #pragma unroll
        for (int s = 0; s < 4; s++) {
            int rl = mrow + (s >> 1) * 16 + (s & 1) * 8 + (lane >> 2);
            rv1[rl * 2 + nh] = B1[s];
            rv2[rl * 2 + nh] = B2[s];
            ri1[rl * 2 + nh] = I1[s];
        }
    }
    __syncthreads();
    if (tid < 128) {
        float a1 = rv1[tid * 2], a2 = rv2[tid * 2];
        int ai = ri1[tid * 2];
        float o1 = rv1[tid * 2 + 1], o2 = rv2[tid * 2 + 1];
        int oi = ri1[tid * 2 + 1];
        float n2 = fminf(fminf(a2, o2), fmaxf(a1, o1));
        if (o1 < a1 || (o1 == a1 && oi < ai)) { a1 = o1; ai = oi; }
        g_b1[row0 + tid] = a1;
        g_b2[row0 + tid] = n2;
        g_i1[row0 + tid] = ai;
    }
}

// ---------------------------------------------------------------------------
// Kernel D0: compact gated rows into g_list; decided rows finalize directly.
// ---------------------------------------------------------------------------
__global__ __launch_bounds__(256) void compact_kernel() {
    int row = blockIdx.x * 256 + threadIdx.x;
    if (row >= NROWS) return;
    if (g_b2[row] - g_b1[row] >= GATE) {
        g_final[row] = g_i1[row];
    } else {
        int pos = atomicAdd(&g_count, 1);
        g_list[pos] = row;
    }
}

// ---------------------------------------------------------------------------
// Kernel D1: candidate-filtered exact rescan. One 128-thr block per gated row.
// Candidates = 64-code half-tiles whose approx min < b1 + GATE; the true
// argmin is provably among them (same 2*eps <= GATE assumption as the gate).
// ---------------------------------------------------------------------------
__global__ __launch_bounds__(128) void rescan_kernel(const float* __restrict__ cb) {
    const int e = blockIdx.x;
    if (e >= g_count) return;
    const int row = g_list[e];
    const int tid = threadIdx.x;

    __shared__ float xs[DIM];
    __shared__ int clist[128];
    __shared__ int ccount;
    __shared__ float rv[128];
    __shared__ int   ri[128];

    if (tid == 0) ccount = 0;
    xs[tid] = g_xn[(size_t)row * DIM + tid];
    __syncthreads();

    const float thr = g_b1[row] + GATE;
    float m = g_tmin[(size_t)row * 128 + tid];
    if (m < thr) { int p = atomicAdd(&ccount, 1); clist[p] = tid; }
    __syncthreads();
    const int nc = ccount;

    float best = FLT_MAX;
    int bidx = 0x7fffffff;
    for (int i = (tid >> 6); i < nc; i += 2) {
        int h = clist[i];
        int code = (h >> 1) * 128 + (h & 1) * 64 + (tid & 63);
        const float4* cp = (const float4*)&cb[(size_t)code * DIM];
        float s0 = 0.f, s1 = 0.f, s2 = 0.f, s3 = 0.f;
        #pragma unroll
        for (int d = 0; d < 32; d += 4) {
            float4 v0 = cp[d + 0], v1 = cp[d + 1], v2 = cp[d + 2], v3 = cp[d + 3];
            s0 = fmaf(v0.x, xs[d * 4 + 0], s0);  s0 = fmaf(v0.y, xs[d * 4 + 1], s0);
            s0 = fmaf(v0.z, xs[d * 4 + 2], s0);  s0 = fmaf(v0.w, xs[d * 4 + 3], s0);
            s1 = fmaf(v1.x, xs[d * 4 + 4], s1);  s1 = fmaf(v1.y, xs[d * 4 + 5], s1);
            s1 = fmaf(v1.z, xs[d * 4 + 6], s1);  s1 = fmaf(v1.w, xs[d * 4 + 7], s1);
            s2 = fmaf(v2.x, xs[d * 4 + 8], s2);  s2 = fmaf(v2.y, xs[d * 4 + 9], s2);
            s2 = fmaf(v2.z, xs[d * 4 + 10], s2); s2 = fmaf(v2.w, xs[d * 4 + 11], s2);
            s3 = fmaf(v3.x, xs[d * 4 + 12], s3); s3 = fmaf(v3.y, xs[d * 4 + 13], s3);
            s3 = fmaf(v3.z, xs[d * 4 + 14], s3); s3 = fmaf(v3.w, xs[d * 4 + 15], s3);
        }
        float dot = (s0 + s1) + (s2 + s3);
        float dist = fmaf(-2.0f, dot, g_e2[code]);
        if (dist < best || (dist == best && code < bidx)) { best = dist; bidx = code; }
    }
    rv[tid] = best; ri[tid] = bidx;
    __syncthreads();
    for (int o = 64; o > 0; o >>= 1) {
        if (tid < o) {
            float v = rv[tid + o]; int ii = ri[tid + o];
            if (v < rv[tid] || (v == rv[tid] && ii < ri[tid])) { rv[tid] = v; ri[tid] = ii; }
        }
        __syncthreads();
    }
    if (tid == 0) g_final[row] = ri[0];
}

// ---------------------------------------------------------------------------
// Kernel E: gather + per-block loss partials (deterministic).
// ---------------------------------------------------------------------------
__global__ __launch_bounds__(256) void gather_kernel(const float* __restrict__ cb,
                                                     float* __restrict__ out) {
    __shared__ float sw[8];
    int warp = threadIdx.x >> 5, lane = threadIdx.x & 31;
    int row = blockIdx.x * 8 + warp;
    int ind = g_final[row];
    float4 c = *(const float4*)&cb[(size_t)ind * DIM + lane * 4];
    float4 xv = *(const float4*)&g_xn[(size_t)row * DIM + lane * 4];
    *(float4*)&out[OUT_Q + (size_t)row * DIM + lane * 4] = c;
    float dx = c.x - xv.x, dy = c.y - xv.y, dz = c.z - xv.z, dw = c.w - xv.w;
    float s = dx * dx + dy * dy + dz * dz + dw * dw;
    #pragma unroll
    for (int o = 16; o > 0; o >>= 1) s += __shfl_xor_sync(0xffffffffu, s, o);
    if (lane == 0) { out[OUT_IND + row] = (float)ind; sw[warp] = s; }
    __syncthreads();
    if (threadIdx.x == 0) {
        float tot = 0.0f;
        #pragma unroll
        for (int w = 0; w < 8; w++) tot += sw[w];
        g_part[blockIdx.x] = tot;
    }
}

__global__ __launch_bounds__(256) void final_kernel(float* __restrict__ out) {
    __shared__ float sp[256];
    int tid = threadIdx.x;
    float s = 0.0f;
    for (int i = tid; i < GATHER_BLOCKS; i += 256) s += g_part[i];
    sp[tid] = s;
    __syncthreads();
    for (int o = 128; o > 0; o >>= 1) {
        if (tid < o) sp[tid] += sp[tid + o];
        __syncthreads();
    }
    if (tid == 0) out[OUT_LOSS] = sp[0] * (1.0f / (float)(NROWS * DIM));
}

// ---------------------------------------------------------------------------
extern "C" void kernel_launch(void* const* d_in, const int* in_sizes, int n_in,
                              void* d_out, int out_size) {
    const float* x = (const float*)d_in[0];
    const float* cb = (const float*)d_in[1];
    float* out = (float*)d_out;

    cudaFuncSetAttribute(nn_kernel, cudaFuncAttributeMaxDynamicSharedMemorySize,
                         NN_SMEM);

    ln_kernel<<<NROWS / 8, 256>>>(x);
    cb_kernel<<<KCODES / 8, 256>>>(cb);
    nn_kernel<<<NN_CTAS, 256, NN_SMEM>>>();
    compact_kernel<<<NROWS / 256, 256>>>();
    rescan_kernel<<<NROWS, 128>>>(cb);
    gather_kernel<<<GATHER_BLOCKS, 256>>>(cb, out);
    final_kernel<<<1, 256>>>(out);
}

// round 7
// speedup vs baseline: 3.0432x; 1.3050x over previous
#include <cuda_runtime.h>
#include <cuda_fp16.h>
#include <cstdint>
#include <cfloat>

// ---------------------------------------------------------------- constants
#define NROWS  16384
#define DIM    128
#define KCODES 8192
#define NN_CTAS 128          // 128 row-tiles of 128
#define NTILE   64           // 64 code-tiles of 128
#define GATE    0.10f

#define OUT_Q    0
#define OUT_IND  (NROWS * DIM)
#define OUT_LOSS (NROWS * DIM + NROWS)
#define GATHER_BLOCKS (NROWS / 8)

// smem layout. Rows padded: 128 fp16 = 256B data + 16B pad = 272B.
#define ROWB    272
#define BLKB    (128 * ROWB)          // 34816 bytes per [128 x 128fp16] block
#define A_OFF   0                     // 1 block (hi only)
#define B_OFF   BLKB                  // 2 buffers x 1 block
#define E2_OFF  (B_OFF + 2 * BLKB)    // 2 x 512B
#define NN_SMEM (E2_OFF + 1024)       // 105472

// ------------------------------------------------------------- device scratch
__device__ __half g_Ahi[NROWS * DIM];
__device__ __half g_Bh[KCODES * DIM];
__device__ float g_xn[NROWS * DIM];
__device__ float g_e2[KCODES];
__device__ float g_b1[NROWS];
__device__ float g_b2[NROWS];
__device__ int   g_i1[NROWS];
__device__ int   g_final[NROWS];
__device__ float g_part[GATHER_BLOCKS];
__device__ int   g_count;
__device__ int   g_list[NROWS];
__device__ float g_tmin[(size_t)NROWS * 128];   // per-row, per-(tile,half) approx min

// ------------------------------------------------------------- PTX helpers
__device__ __forceinline__ uint32_t smem_to_u32(const void* p) {
    uint32_t a;
    asm("{ .reg .u64 t; cvta.to.shared.u64 t, %1; cvt.u32.u64 %0, t; }"
        : "=r"(a) : "l"(p));
    return a;
}
#define CP_ASYNC16(dst, src) \
    asm volatile("cp.async.cg.shared.global [%0], [%1], 16;" \
                 :: "r"(dst), "l"(src) : "memory")
#define CP_COMMIT() asm volatile("cp.async.commit_group;" ::: "memory")
#define CP_WAIT0()  asm volatile("cp.async.wait_group 0;" ::: "memory")

#define LDSM_X4(r0, r1, r2, r3, addr) \
    asm volatile("ldmatrix.sync.aligned.m8n8.x4.shared.b16 {%0,%1,%2,%3}, [%4];" \
                 : "=r"(r0), "=r"(r1), "=r"(r2), "=r"(r3) : "r"(addr))

__device__ __forceinline__ void mma16816(float* c, const uint32_t* a,
                                         uint32_t b0, uint32_t b1) {
    asm volatile(
        "mma.sync.aligned.m16n8k16.row.col.f32.f16.f16.f32 "
        "{%0,%1,%2,%3}, {%4,%5,%6,%7}, {%8,%9}, {%0,%1,%2,%3};"
        : "+f"(c[0]), "+f"(c[1]), "+f"(c[2]), "+f"(c[3])
        : "r"(a[0]), "r"(a[1]), "r"(a[2]), "r"(a[3]), "r"(b0), "r"(b1));
}

// ---------------------------------------------------------------------------
// Kernel A: layernorm -> g_xn (f32) + fp16 hi. 1 row per warp.
// ---------------------------------------------------------------------------
__global__ __launch_bounds__(256) void ln_kernel(const float* __restrict__ x) {
    if (blockIdx.x == 0 && threadIdx.x == 0) g_count = 0;
    int warp = threadIdx.x >> 5, lane = threadIdx.x & 31;
    int row = blockIdx.x * 8 + warp;
    float4 v = *(const float4*)&x[(size_t)row * DIM + lane * 4];
    float s = v.x + v.y + v.z + v.w;
    #pragma unroll
    for (int o = 16; o > 0; o >>= 1) s += __shfl_xor_sync(0xffffffffu, s, o);
    float mu = s * (1.0f / 128.0f);
    float dx = v.x - mu, dy = v.y - mu, dz = v.z - mu, dw = v.w - mu;
    float q = dx * dx + dy * dy + dz * dz + dw * dw;
    #pragma unroll
    for (int o = 16; o > 0; o >>= 1) q += __shfl_xor_sync(0xffffffffu, q, o);
    float rs = rsqrtf(q * (1.0f / 128.0f) + 1e-5f);
    float y[4] = {dx * rs, dy * rs, dz * rs, dw * rs};
    *(float4*)&g_xn[(size_t)row * DIM + lane * 4] = make_float4(y[0], y[1], y[2], y[3]);
    __half h[4] = {__float2half(y[0]), __float2half(y[1]),
                   __float2half(y[2]), __float2half(y[3])};
    *(uint2*)&g_Ahi[(size_t)row * DIM + lane * 4] = *(uint2*)h;
}

// ---------------------------------------------------------------------------
// Kernel B: codebook -> e2 (exact f32) + fp16 hi. 1 code per warp.
// ---------------------------------------------------------------------------
__global__ __launch_bounds__(256) void cb_kernel(const float* __restrict__ cb) {
    int warp = threadIdx.x >> 5, lane = threadIdx.x & 31;
    int row = blockIdx.x * 8 + warp;
    float4 v = *(const float4*)&cb[(size_t)row * DIM + lane * 4];
    float q = v.x * v.x + v.y * v.y + v.z * v.z + v.w * v.w;
    #pragma unroll
    for (int o = 16; o > 0; o >>= 1) q += __shfl_xor_sync(0xffffffffu, q, o);
    if (lane == 0) g_e2[row] = q;
    __half h[4] = {__float2half(v.x), __float2half(v.y),
                   __float2half(v.z), __float2half(v.w)};
    *(uint2*)&g_Bh[(size_t)row * DIM + lane * 4] = *(uint2*)h;
}

// ---------------------------------------------------------------------------
// Kernel C: HMMA fp16 hi-only distance GEMM (K=128) + top-2 + per-half-tile min.
// ---------------------------------------------------------------------------
__global__ __launch_bounds__(256, 1) void nn_kernel() {
    extern __shared__ char sptr[];
    const uint32_t sbase = smem_to_u32(sptr);
    const int tid = threadIdx.x;
    const int lane = tid & 31;
    const int w = tid >> 5;
    const int mrow = (w & 3) * 32;
    const int ncol0 = (w >> 2) * 64;
    const int row0 = blockIdx.x * 128;

    // A tile (once): 1 block (hi)
    #pragma unroll
    for (int i = 0; i < 8; i++) {
        int idx = i * 256 + tid;
        int r = (idx >> 4) & 127;
        int u = idx & 15;
        uint4 v = *(const uint4*)(g_Ahi + (size_t)(row0 + r) * DIM + u * 8);
        *(uint4*)(sptr + A_OFF + r * ROWB + u * 16) = v;
    }
    // B tile 0 (1 block) + e2 slot 0
    {
        uint32_t bb = sbase + B_OFF;
        #pragma unroll
        for (int i = 0; i < 8; i++) {
            int idx = i * 256 + tid;
            int r = (idx >> 4) & 127;
            int u = idx & 15;
            CP_ASYNC16(bb + r * ROWB + u * 16, g_Bh + (size_t)r * DIM + u * 8);
        }
        if (tid < 32) CP_ASYNC16(sbase + E2_OFF + tid * 16, (const char*)g_e2 + tid * 16);
        CP_COMMIT();
    }

    float B1[4], B2[4];
    int I1[4];
    #pragma unroll
    for (int s = 0; s < 4; s++) { B1[s] = FLT_MAX; B2[s] = FLT_MAX; I1[s] = 0; }

    const uint32_t a_row = mrow + (lane & 15);
    const uint32_t a_cb = (lane >> 4) << 4;
    const uint32_t b_row = ncol0 + (lane & 7) + ((lane & 16) >> 1);
    const uint32_t b_k8 = (lane & 8);

    for (int t = 0; t < NTILE; t++) {
        CP_WAIT0();
        __syncthreads();
        if (t + 1 < NTILE) {
            uint32_t bb = sbase + B_OFF + ((t + 1) & 1) * BLKB;
            const size_t crow0 = (size_t)(t + 1) * 128;
            #pragma unroll
            for (int i = 0; i < 8; i++) {
                int idx = i * 256 + tid;
                int r = (idx >> 4) & 127;
                int u = idx & 15;
                CP_ASYNC16(bb + r * ROWB + u * 16, g_Bh + (crow0 + r) * DIM + u * 8);
            }
            if (tid < 32)
                CP_ASYNC16(sbase + E2_OFF + ((t + 1) & 1) * 512 + tid * 16,
                           (const char*)(g_e2 + (t + 1) * 128) + tid * 16);
            CP_COMMIT();
        }

        const uint32_t bufB = sbase + B_OFF + (t & 1) * BLKB;
        float c[2][8][4];
        #pragma unroll
        for (int mb = 0; mb < 2; mb++)
            #pragma unroll
            for (int nb = 0; nb < 8; nb++)
                #pragma unroll
                for (int q = 0; q < 4; q++) c[mb][nb][q] = 0.0f;

        #pragma unroll
        for (int j = 0; j < 8; j++) {
            const int kk = j * 16;
            uint32_t a[2][4];
            #pragma unroll
            for (int mb = 0; mb < 2; mb++) {
                uint32_t addr = sbase + A_OFF +
                                (a_row + mb * 16) * ROWB + kk * 2 + a_cb;
                LDSM_X4(a[mb][0], a[mb][1], a[mb][2], a[mb][3], addr);
            }
            uint32_t b[4][4];
            #pragma unroll
            for (int nb4 = 0; nb4 < 4; nb4++) {
                uint32_t addr = bufB +
                                (b_row + nb4 * 16) * ROWB + (kk + b_k8) * 2;
                LDSM_X4(b[nb4][0], b[nb4][1], b[nb4][2], b[nb4][3], addr);
            }
            #pragma unroll
            for (int mb = 0; mb < 2; mb++)
                #pragma unroll
                for (int nb = 0; nb < 8; nb++)
                    mma16816(c[mb][nb], a[mb],
                             b[nb >> 1][(nb & 1) * 2], b[nb >> 1][(nb & 1) * 2 + 1]);
        }

        const float* e2p = (const float*)(sptr + E2_OFF + (t & 1) * 512);
        const int colb = ncol0 + 2 * (lane & 3);
        float tm[4] = {FLT_MAX, FLT_MAX, FLT_MAX, FLT_MAX};
        #pragma unroll
        for (int nb = 0; nb < 8; nb++) {
            float2 ev = *(const float2*)&e2p[colb + nb * 8];
            int gidx = t * 128 + colb + nb * 8;
            #pragma unroll
            for (int mb = 0; mb < 2; mb++)
                #pragma unroll
                for (int hi = 0; hi < 2; hi++) {
                    int s = mb * 2 + hi;
                    float d0 = fmaf(-2.0f, c[mb][nb][hi * 2 + 0], ev.x);
                    float d1 = fmaf(-2.0f, c[mb][nb][hi * 2 + 1], ev.y);
                    tm[s] = fminf(tm[s], fminf(d0, d1));
                    if (d0 < B1[s]) { B2[s] = B1[s]; B1[s] = d0; I1[s] = gidx; }
                    else if (d0 < B2[s]) { B2[s] = d0; }
                    if (d1 < B1[s]) { B2[s] = B1[s]; B1[s] = d1; I1[s] = gidx + 1; }
                    else if (d1 < B2[s]) { B2[s] = d1; }
                }
        }
        // per-(row, tile, warp-half) approx min -> gmem
        #pragma unroll
        for (int s = 0; s < 4; s++) {
            float m = tm[s];
            m = fminf(m, __shfl_xor_sync(0xffffffffu, m, 1));
            m = fminf(m, __shfl_xor_sync(0xffffffffu, m, 2));
            if ((lane & 3) == 0) {
                int rl = mrow + (s >> 1) * 16 + (s & 1) * 8 + (lane >> 2);
                g_tmin[(size_t)(row0 + rl) * 128 + t * 2 + (w >> 2)] = m;
            }
        }
    }

    #pragma unroll
    for (int s = 0; s < 4; s++) {
        #pragma unroll
        for (int off = 1; off < 4; off <<= 1) {
            float ob1 = __shfl_xor_sync(0xffffffffu, B1[s], off);
            float ob2 = __shfl_xor_sync(0xffffffffu, B2[s], off);
            int oi1 = __shfl_xor_sync(0xffffffffu, I1[s], off);
            float nb2 = fminf(fminf(B2[s], ob2), fmaxf(B1[s], ob1));
            if (ob1 < B1[s] || (ob1 == B1[s] && oi1 < I1[s])) { B1[s] = ob1; I1[s] = oi1; }
            B2[s] = nb2;
        }
    }
    __syncthreads();
    float* rv1 = (float*)sptr;
    float* rv2 = rv1 + 256;
    int*   ri1 = (int*)(rv2 + 256);
    if ((lane & 3) == 0) {
        int nh = w >> 2;
        #pragma unroll
        for (int s = 0; s < 4; s++) {
            int rl = mrow + (s >> 1) * 16 + (s & 1) * 8 + (lane >> 2);
            rv1[rl * 2 + nh] = B1[s];
            rv2[rl * 2 + nh] = B2[s];
            ri1[rl * 2 + nh] = I1[s];
        }
    }
    __syncthreads();
    if (tid < 128) {
        float a1 = rv1[tid * 2], a2 = rv2[tid * 2];
        int ai = ri1[tid * 2];
        float o1 = rv1[tid * 2 + 1], o2 = rv2[tid * 2 + 1];
        int oi = ri1[tid * 2 + 1];
        float n2 = fminf(fminf(a2, o2), fmaxf(a1, o1));
        if (o1 < a1 || (o1 == a1 && oi < ai)) { a1 = o1; ai = oi; }
        g_b1[row0 + tid] = a1;
        g_b2[row0 + tid] = n2;
        g_i1[row0 + tid] = ai;
    }
}

// ---------------------------------------------------------------------------
// Kernel D0: compact gated rows into g_list; decided rows finalize directly.
// ---------------------------------------------------------------------------
__global__ __launch_bounds__(256) void compact_kernel() {
    int row = blockIdx.x * 256 + threadIdx.x;
    if (row >= NROWS) return;
    if (g_b2[row] - g_b1[row] >= GATE) {
        g_final[row] = g_i1[row];
    } else {
        int pos = atomicAdd(&g_count, 1);
        g_list[pos] = row;
    }
}

// ---------------------------------------------------------------------------
// Kernel D1: candidate-filtered exact rescan. One 128-thr block per gated row.
// Candidates = 64-code half-tiles whose approx min < b1 + GATE.
// ---------------------------------------------------------------------------
__global__ __launch_bounds__(128) void rescan_kernel(const float* __restrict__ cb) {
    const int e = blockIdx.x;
    if (e >= g_count) return;
    const int row = g_list[e];
    const int tid = threadIdx.x;

    __shared__ float xs[DIM];
    __shared__ int clist[128];
    __shared__ int ccount;
    __shared__ float rv[128];
    __shared__ int   ri[128];

    if (tid == 0) ccount = 0;
    xs[tid] = g_xn[(size_t)row * DIM + tid];
    __syncthreads();

    const float thr = g_b1[row] + GATE;
    float m = g_tmin[(size_t)row * 128 + tid];
    if (m < thr) { int p = atomicAdd(&ccount, 1); clist[p] = tid; }
    __syncthreads();
    const int nc = ccount;

    float best = FLT_MAX;
    int bidx = 0x7fffffff;
    for (int i = (tid >> 6); i < nc; i += 2) {
        int h = clist[i];
        int code = (h >> 1) * 128 + (h & 1) * 64 + (tid & 63);
        const float4* cp = (const float4*)&cb[(size_t)code * DIM];
        float s0 = 0.f, s1 = 0.f, s2 = 0.f, s3 = 0.f;
        #pragma unroll
        for (int d = 0; d < 32; d += 4) {
            float4 v0 = cp[d + 0], v1 = cp[d + 1], v2 = cp[d + 2], v3 = cp[d + 3];
            s0 = fmaf(v0.x, xs[d * 4 + 0], s0);  s0 = fmaf(v0.y, xs[d * 4 + 1], s0);
            s0 = fmaf(v0.z, xs[d * 4 + 2], s0);  s0 = fmaf(v0.w, xs[d * 4 + 3], s0);
            s1 = fmaf(v1.x, xs[d * 4 + 4], s1);  s1 = fmaf(v1.y, xs[d * 4 + 5], s1);
            s1 = fmaf(v1.z, xs[d * 4 + 6], s1);  s1 = fmaf(v1.w, xs[d * 4 + 7], s1);
            s2 = fmaf(v2.x, xs[d * 4 + 8], s2);  s2 = fmaf(v2.y, xs[d * 4 + 9], s2);
            s2 = fmaf(v2.z, xs[d * 4 + 10], s2); s2 = fmaf(v2.w, xs[d * 4 + 11], s2);
            s3 = fmaf(v3.x, xs[d * 4 + 12], s3); s3 = fmaf(v3.y, xs[d * 4 + 13], s3);
            s3 = fmaf(v3.z, xs[d * 4 + 14], s3); s3 = fmaf(v3.w, xs[d * 4 + 15], s3);
        }
        float dot = (s0 + s1) + (s2 + s3);
        float dist = fmaf(-2.0f, dot, g_e2[code]);
        if (dist < best || (dist == best && code < bidx)) { best = dist; bidx = code; }
    }
    rv[tid] = best; ri[tid] = bidx;
    __syncthreads();
    for (int o = 64; o > 0; o >>= 1) {
        if (tid < o) {
            float v = rv[tid + o]; int ii = ri[tid + o];
            if (v < rv[tid] || (v == rv[tid] && ii < ri[tid])) { rv[tid] = v; ri[tid] = ii; }
        }
        __syncthreads();
    }
    if (tid == 0) g_final[row] = ri[0];
}

// ---------------------------------------------------------------------------
// Kernel E: gather + per-block loss partials (deterministic).
// ---------------------------------------------------------------------------
__global__ __launch_bounds__(256) void gather_kernel(const float* __restrict__ cb,
                                                     float* __restrict__ out) {
    __shared__ float sw[8];
    int warp = threadIdx.x >> 5, lane = threadIdx.x & 31;
    int row = blockIdx.x * 8 + warp;
    int ind = g_final[row];
    float4 c = *(const float4*)&cb[(size_t)ind * DIM + lane * 4];
    float4 xv = *(const float4*)&g_xn[(size_t)row * DIM + lane * 4];
    *(float4*)&out[OUT_Q + (size_t)row * DIM + lane * 4] = c;
    float dx = c.x - xv.x, dy = c.y - xv.y, dz = c.z - xv.z, dw = c.w - xv.w;
    float s = dx * dx + dy * dy + dz * dz + dw * dw;
    #pragma unroll
    for (int o = 16; o > 0; o >>= 1) s += __shfl_xor_sync(0xffffffffu, s, o);
    if (lane == 0) { out[OUT_IND + row] = (float)ind; sw[warp] = s; }
    __syncthreads();
    if (threadIdx.x == 0) {
        float tot = 0.0f;
        #pragma unroll
        for (int w = 0; w < 8; w++) tot += sw[w];
        g_part[blockIdx.x] = tot;
    }
}

__global__ __launch_bounds__(256) void final_kernel(float* __restrict__ out) {
    __shared__ float sp[256];
    int tid = threadIdx.x;
    float s = 0.0f;
    for (int i = tid; i < GATHER_BLOCKS; i += 256) s += g_part[i];
    sp[tid] = s;
    __syncthreads();
    for (int o = 128; o > 0; o >>= 1) {
        if (tid < o) sp[tid] += sp[tid + o];
        __syncthreads();
    }
    if (tid == 0) out[OUT_LOSS] = sp[0] * (1.0f / (float)(NROWS * DIM));
}

// ---------------------------------------------------------------------------
extern "C" void kernel_launch(void* const* d_in, const int* in_sizes, int n_in,
                              void* d_out, int out_size) {
    const float* x = (const float*)d_in[0];
    const float* cb = (const float*)d_in[1];
    float* out = (float*)d_out;

    cudaFuncSetAttribute(nn_kernel, cudaFuncAttributeMaxDynamicSharedMemorySize,
                         NN_SMEM);

    ln_kernel<<<NROWS / 8, 256>>>(x);
    cb_kernel<<<KCODES / 8, 256>>>(cb);
    nn_kernel<<<NN_CTAS, 256, NN_SMEM>>>();
    compact_kernel<<<NROWS / 256, 256>>>();
    rescan_kernel<<<NROWS, 128>>>(cb);
    gather_kernel<<<GATHER_BLOCKS, 256>>>(cb, out);
    final_kernel<<<1, 256>>>(out);
}

// round 8
// speedup vs baseline: 3.1939x; 1.0495x over previous
#include <cuda_runtime.h>
#include <cuda_fp16.h>
#include <cstdint>
#include <cfloat>

// ---------------------------------------------------------------- constants
#define NROWS  16384
#define DIM    128
#define KCODES 8192
#define GATE    0.10f

#define NCHUNK  8            // code chunks per row-tile
#define CTILES  8            // tiles per chunk (64 total / 8)
#define NN_GRID (128 * NCHUNK)

#define OUT_Q    0
#define OUT_IND  (NROWS * DIM)
#define OUT_LOSS (NROWS * DIM + NROWS)
#define GATHER_BLOCKS (NROWS / 8)

// smem layout. Rows padded: 128 fp16 = 256B data + 16B pad = 272B.
#define ROWB    272
#define BLKB    (128 * ROWB)          // 34816 bytes per [128 x 128fp16] block
#define A_OFF   0                     // 1 block (hi only)
#define B_OFF   BLKB                  // 2 buffers x 1 block
#define E2_OFF  (B_OFF + 2 * BLKB)    // 2 x 512B
#define NN_SMEM (E2_OFF + 1024)       // 105472

// ------------------------------------------------------------- device scratch
__device__ __half g_Ahi[NROWS * DIM];
__device__ __half g_Bh[KCODES * DIM];
__device__ float g_xn[NROWS * DIM];
__device__ float g_e2[KCODES];
__device__ float g_pb1[(size_t)NROWS * NCHUNK];
__device__ float g_pb2[(size_t)NROWS * NCHUNK];
__device__ int   g_pi1[(size_t)NROWS * NCHUNK];
__device__ float g_b1[NROWS];
__device__ int   g_final[NROWS];
__device__ float g_part[GATHER_BLOCKS];
__device__ int   g_count;
__device__ int   g_list[NROWS];
__device__ float g_tmin[(size_t)NROWS * 128];   // per-row, per-(tile,half) approx min

// ------------------------------------------------------------- PTX helpers
__device__ __forceinline__ uint32_t smem_to_u32(const void* p) {
    uint32_t a;
    asm("{ .reg .u64 t; cvta.to.shared.u64 t, %1; cvt.u32.u64 %0, t; }"
        : "=r"(a) : "l"(p));
    return a;
}
#define CP_ASYNC16(dst, src) \
    asm volatile("cp.async.cg.shared.global [%0], [%1], 16;" \
                 :: "r"(dst), "l"(src) : "memory")
#define CP_COMMIT() asm volatile("cp.async.commit_group;" ::: "memory")
#define CP_WAIT0()  asm volatile("cp.async.wait_group 0;" ::: "memory")

#define LDSM_X4(r0, r1, r2, r3, addr) \
    asm volatile("ldmatrix.sync.aligned.m8n8.x4.shared.b16 {%0,%1,%2,%3}, [%4];" \
                 : "=r"(r0), "=r"(r1), "=r"(r2), "=r"(r3) : "r"(addr))

__device__ __forceinline__ void mma16816(float* c, const uint32_t* a,
                                         uint32_t b0, uint32_t b1) {
    asm volatile(
        "mma.sync.aligned.m16n8k16.row.col.f32.f16.f16.f32 "
        "{%0,%1,%2,%3}, {%4,%5,%6,%7}, {%8,%9}, {%0,%1,%2,%3};"
        : "+f"(c[0]), "+f"(c[1]), "+f"(c[2]), "+f"(c[3])
        : "r"(a[0]), "r"(a[1]), "r"(a[2]), "r"(a[3]), "r"(b0), "r"(b1));
}

// ---------------------------------------------------------------------------
// Kernel A: layernorm -> g_xn (f32) + fp16 hi. 1 row per warp.
// ---------------------------------------------------------------------------
__global__ __launch_bounds__(256) void ln_kernel(const float* __restrict__ x) {
    if (blockIdx.x == 0 && threadIdx.x == 0) g_count = 0;
    int warp = threadIdx.x >> 5, lane = threadIdx.x & 31;
    int row = blockIdx.x * 8 + warp;
    float4 v = *(const float4*)&x[(size_t)row * DIM + lane * 4];
    float s = v.x + v.y + v.z + v.w;
    #pragma unroll
    for (int o = 16; o > 0; o >>= 1) s += __shfl_xor_sync(0xffffffffu, s, o);
    float mu = s * (1.0f / 128.0f);
    float dx = v.x - mu, dy = v.y - mu, dz = v.z - mu, dw = v.w - mu;
    float q = dx * dx + dy * dy + dz * dz + dw * dw;
    #pragma unroll
    for (int o = 16; o > 0; o >>= 1) q += __shfl_xor_sync(0xffffffffu, q, o);
    float rs = rsqrtf(q * (1.0f / 128.0f) + 1e-5f);
    float y[4] = {dx * rs, dy * rs, dz * rs, dw * rs};
    *(float4*)&g_xn[(size_t)row * DIM + lane * 4] = make_float4(y[0], y[1], y[2], y[3]);
    __half h[4] = {__float2half(y[0]), __float2half(y[1]),
                   __float2half(y[2]), __float2half(y[3])};
    *(uint2*)&g_Ahi[(size_t)row * DIM + lane * 4] = *(uint2*)h;
}

// ---------------------------------------------------------------------------
// Kernel B: codebook -> e2 (exact f32) + fp16 hi. 1 code per warp.
// ---------------------------------------------------------------------------
__global__ __launch_bounds__(256) void cb_kernel(const float* __restrict__ cb) {
    int warp = threadIdx.x >> 5, lane = threadIdx.x & 31;
    int row = blockIdx.x * 8 + warp;
    float4 v = *(const float4*)&cb[(size_t)row * DIM + lane * 4];
    float q = v.x * v.x + v.y * v.y + v.z * v.z + v.w * v.w;
    #pragma unroll
    for (int o = 16; o > 0; o >>= 1) q += __shfl_xor_sync(0xffffffffu, q, o);
    if (lane == 0) g_e2[row] = q;
    __half h[4] = {__float2half(v.x), __float2half(v.y),
                   __float2half(v.z), __float2half(v.w)};
    *(uint2*)&g_Bh[(size_t)row * DIM + lane * 4] = *(uint2*)h;
}

// ---------------------------------------------------------------------------
// Kernel C: HMMA fp16 hi-only distance GEMM, chunked for SM utilization.
// Grid 1024 = 8 chunks (major) x 128 row-tiles. Each CTA: 128 rows x 8 tiles.
// A ldmatrix fragments hoisted to registers (reused across the 8 tiles).
// ---------------------------------------------------------------------------
__global__ __launch_bounds__(256, 1) void nn_kernel() {
    extern __shared__ char sptr[];
    const uint32_t sbase = smem_to_u32(sptr);
    const int tid = threadIdx.x;
    const int lane = tid & 31;
    const int w = tid >> 5;
    const int mrow = (w & 3) * 32;
    const int ncol0 = (w >> 2) * 64;
    const int chunk = blockIdx.x >> 7;          // chunk-major: L2 B-tile reuse
    const int rb = blockIdx.x & 127;
    const int row0 = rb * 128;
    const int tile0 = chunk * CTILES;

    // A tile: 1 block (hi)
    #pragma unroll
    for (int i = 0; i < 8; i++) {
        int idx = i * 256 + tid;
        int r = (idx >> 4) & 127;
        int u = idx & 15;
        uint4 v = *(const uint4*)(g_Ahi + (size_t)(row0 + r) * DIM + u * 8);
        *(uint4*)(sptr + A_OFF + r * ROWB + u * 16) = v;
    }
    // B tile tile0 + e2 slot 0
    {
        uint32_t bb = sbase + B_OFF;
        const size_t crow0 = (size_t)tile0 * 128;
        #pragma unroll
        for (int i = 0; i < 8; i++) {
            int idx = i * 256 + tid;
            int r = (idx >> 4) & 127;
            int u = idx & 15;
            CP_ASYNC16(bb + r * ROWB + u * 16, g_Bh + (crow0 + r) * DIM + u * 8);
        }
        if (tid < 32)
            CP_ASYNC16(sbase + E2_OFF + tid * 16,
                       (const char*)(g_e2 + tile0 * 128) + tid * 16);
        CP_COMMIT();
    }

    const uint32_t a_row = mrow + (lane & 15);
    const uint32_t a_cb = (lane >> 4) << 4;
    const uint32_t b_row = ncol0 + (lane & 7) + ((lane & 16) >> 1);
    const uint32_t b_k8 = (lane & 8);

    // ---- hoist A fragments (needs A smem ready)
    __syncthreads();
    uint32_t af[8][2][4];
    #pragma unroll
    for (int j = 0; j < 8; j++)
        #pragma unroll
        for (int mb = 0; mb < 2; mb++) {
            uint32_t addr = sbase + A_OFF +
                            (a_row + mb * 16) * ROWB + j * 32 + a_cb;
            LDSM_X4(af[j][mb][0], af[j][mb][1], af[j][mb][2], af[j][mb][3], addr);
        }

    float B1[4], B2[4];
    int I1[4];
    #pragma unroll
    for (int s = 0; s < 4; s++) { B1[s] = FLT_MAX; B2[s] = FLT_MAX; I1[s] = 0; }

    for (int t = 0; t < CTILES; t++) {
        const int gt = tile0 + t;
        CP_WAIT0();
        __syncthreads();
        if (t + 1 < CTILES) {
            uint32_t bb = sbase + B_OFF + ((t + 1) & 1) * BLKB;
            const size_t crow0 = (size_t)(gt + 1) * 128;
            #pragma unroll
            for (int i = 0; i < 8; i++) {
                int idx = i * 256 + tid;
                int r = (idx >> 4) & 127;
                int u = idx & 15;
                CP_ASYNC16(bb + r * ROWB + u * 16, g_Bh + (crow0 + r) * DIM + u * 8);
            }
            if (tid < 32)
                CP_ASYNC16(sbase + E2_OFF + ((t + 1) & 1) * 512 + tid * 16,
                           (const char*)(g_e2 + (gt + 1) * 128) + tid * 16);
            CP_COMMIT();
        }

        const uint32_t bufB = sbase + B_OFF + (t & 1) * BLKB;
        float c[2][8][4];
        #pragma unroll
        for (int mb = 0; mb < 2; mb++)
            #pragma unroll
            for (int nb = 0; nb < 8; nb++)
                #pragma unroll
                for (int q = 0; q < 4; q++) c[mb][nb][q] = 0.0f;

        #pragma unroll
        for (int j = 0; j < 8; j++) {
            const int kk = j * 16;
            uint32_t b[4][4];
            #pragma unroll
            for (int nb4 = 0; nb4 < 4; nb4++) {
                uint32_t addr = bufB +
                                (b_row + nb4 * 16) * ROWB + (kk + b_k8) * 2;
                LDSM_X4(b[nb4][0], b[nb4][1], b[nb4][2], b[nb4][3], addr);
            }
            #pragma unroll
            for (int mb = 0; mb < 2; mb++)
                #pragma unroll
                for (int nb = 0; nb < 8; nb++)
                    mma16816(c[mb][nb], af[j][mb],
                             b[nb >> 1][(nb & 1) * 2], b[nb >> 1][(nb & 1) * 2 + 1]);
        }

        const float* e2p = (const float*)(sptr + E2_OFF + (t & 1) * 512);
        const int colb = ncol0 + 2 * (lane & 3);
        float tm[4] = {FLT_MAX, FLT_MAX, FLT_MAX, FLT_MAX};
        #pragma unroll
        for (int nb = 0; nb < 8; nb++) {
            float2 ev = *(const float2*)&e2p[colb + nb * 8];
            int gidx = gt * 128 + colb + nb * 8;
            #pragma unroll
            for (int mb = 0; mb < 2; mb++)
                #pragma unroll
                for (int hi = 0; hi < 2; hi++) {
                    int s = mb * 2 + hi;
                    float d0 = fmaf(-2.0f, c[mb][nb][hi * 2 + 0], ev.x);
                    float d1 = fmaf(-2.0f, c[mb][nb][hi * 2 + 1], ev.y);
                    tm[s] = fminf(tm[s], fminf(d0, d1));
                    if (d0 < B1[s]) { B2[s] = B1[s]; B1[s] = d0; I1[s] = gidx; }
                    else if (d0 < B2[s]) { B2[s] = d0; }
                    if (d1 < B1[s]) { B2[s] = B1[s]; B1[s] = d1; I1[s] = gidx + 1; }
                    else if (d1 < B2[s]) { B2[s] = d1; }
                }
        }
        #pragma unroll
        for (int s = 0; s < 4; s++) {
            float m = tm[s];
            m = fminf(m, __shfl_xor_sync(0xffffffffu, m, 1));
            m = fminf(m, __shfl_xor_sync(0xffffffffu, m, 2));
            if ((lane & 3) == 0) {
                int rl = mrow + (s >> 1) * 16 + (s & 1) * 8 + (lane >> 2);
                g_tmin[(size_t)(row0 + rl) * 128 + gt * 2 + (w >> 2)] = m;
            }
        }
    }

    #pragma unroll
    for (int s = 0; s < 4; s++) {
        #pragma unroll
        for (int off = 1; off < 4; off <<= 1) {
            float ob1 = __shfl_xor_sync(0xffffffffu, B1[s], off);
            float ob2 = __shfl_xor_sync(0xffffffffu, B2[s], off);
            int oi1 = __shfl_xor_sync(0xffffffffu, I1[s], off);
            float nb2 = fminf(fminf(B2[s], ob2), fmaxf(B1[s], ob1));
            if (ob1 < B1[s] || (ob1 == B1[s] && oi1 < I1[s])) { B1[s] = ob1; I1[s] = oi1; }
            B2[s] = nb2;
        }
    }
    __syncthreads();
    float* rv1 = (float*)sptr;
    float* rv2 = rv1 + 256;
    int*   ri1 = (int*)(rv2 + 256);
    if ((lane & 3) == 0) {
        int nh = w >> 2;
        #pragma unroll
        for (int s = 0; s < 4; s++) {
            int rl = mrow + (s >> 1) * 16 + (s & 1) * 8 + (lane >> 2);
            rv1[rl * 2 + nh] = B1[s];
            rv2[rl * 2 + nh] = B2[s];
            ri1[rl * 2 + nh] = I1[s];
        }
    }
    __syncthreads();
    if (tid < 128) {
        float a1 = rv1[tid * 2], a2 = rv2[tid * 2];
        int ai = ri1[tid * 2];
        float o1 = rv1[tid * 2 + 1], o2 = rv2[tid * 2 + 1];
        int oi = ri1[tid * 2 + 1];
        float n2 = fminf(fminf(a2, o2), fmaxf(a1, o1));
        if (o1 < a1 || (o1 == a1 && oi < ai)) { a1 = o1; ai = oi; }
        size_t e = (size_t)(row0 + tid) * NCHUNK + chunk;
        g_pb1[e] = a1;
        g_pb2[e] = n2;
        g_pi1[e] = ai;
    }
}

// ---------------------------------------------------------------------------
// Kernel D0: combine chunk partials, gate, and compact gated rows.
// ---------------------------------------------------------------------------
__global__ __launch_bounds__(256) void combine_kernel() {
    int row = blockIdx.x * 256 + threadIdx.x;
    if (row >= NROWS) return;
    float B1v = FLT_MAX, B2v = FLT_MAX;
    int I1v = 0x7fffffff;
    #pragma unroll
    for (int c = 0; c < NCHUNK; c++) {
        size_t e = (size_t)row * NCHUNK + c;
        float b1 = g_pb1[e], b2 = g_pb2[e];
        int i1 = g_pi1[e];
        if (b1 < B1v || (b1 == B1v && i1 < I1v)) {
            B2v = fminf(B1v, b2);
            B1v = b1; I1v = i1;
        } else {
            B2v = fminf(B2v, b1);
        }
    }
    g_b1[row] = B1v;
    if (B2v - B1v >= GATE) {
        g_final[row] = I1v;
    } else {
        int pos = atomicAdd(&g_count, 1);
        g_list[pos] = row;
    }
}

// ---------------------------------------------------------------------------
// Kernel D1: candidate-filtered exact rescan. One 128-thr block per gated row.
// ---------------------------------------------------------------------------
__global__ __launch_bounds__(128) void rescan_kernel(const float* __restrict__ cb) {
    const int e = blockIdx.x;
    if (e >= g_count) return;
    const int row = g_list[e];
    const int tid = threadIdx.x;

    __shared__ float xs[DIM];
    __shared__ int clist[128];
    __shared__ int ccount;
    __shared__ float rv[128];
    __shared__ int   ri[128];

    if (tid == 0) ccount = 0;
    xs[tid] = g_xn[(size_t)row * DIM + tid];
    __syncthreads();

    const float thr = g_b1[row] + GATE;
    float m = g_tmin[(size_t)row * 128 + tid];
    if (m < thr) { int p = atomicAdd(&ccount, 1); clist[p] = tid; }
    __syncthreads();
    const int nc = ccount;

    float best = FLT_MAX;
    int bidx = 0x7fffffff;
    for (int i = (tid >> 6); i < nc; i += 2) {
        int h = clist[i];
        int code = (h >> 1) * 128 + (h & 1) * 64 + (tid & 63);
        const float4* cp = (const float4*)&cb[(size_t)code * DIM];
        float s0 = 0.f, s1 = 0.f, s2 = 0.f, s3 = 0.f;
        #pragma unroll
        for (int d = 0; d < 32; d += 4) {
            float4 v0 = cp[d + 0], v1 = cp[d + 1], v2 = cp[d + 2], v3 = cp[d + 3];
            s0 = fmaf(v0.x, xs[d * 4 + 0], s0);  s0 = fmaf(v0.y, xs[d * 4 + 1], s0);
            s0 = fmaf(v0.z, xs[d * 4 + 2], s0);  s0 = fmaf(v0.w, xs[d * 4 + 3], s0);
            s1 = fmaf(v1.x, xs[d * 4 + 4], s1);  s1 = fmaf(v1.y, xs[d * 4 + 5], s1);
            s1 = fmaf(v1.z, xs[d * 4 + 6], s1);  s1 = fmaf(v1.w, xs[d * 4 + 7], s1);
            s2 = fmaf(v2.x, xs[d * 4 + 8], s2);  s2 = fmaf(v2.y, xs[d * 4 + 9], s2);
            s2 = fmaf(v2.z, xs[d * 4 + 10], s2); s2 = fmaf(v2.w, xs[d * 4 + 11], s2);
            s3 = fmaf(v3.x, xs[d * 4 + 12], s3); s3 = fmaf(v3.y, xs[d * 4 + 13], s3);
            s3 = fmaf(v3.z, xs[d * 4 + 14], s3); s3 = fmaf(v3.w, xs[d * 4 + 15], s3);
        }
        float dot = (s0 + s1) + (s2 + s3);
        float dist = fmaf(-2.0f, dot, g_e2[code]);
        if (dist < best || (dist == best && code < bidx)) { best = dist; bidx = code; }
    }
    rv[tid] = best; ri[tid] = bidx;
    __syncthreads();
    for (int o = 64; o > 0; o >>= 1) {
        if (tid < o) {
            float v = rv[tid + o]; int ii = ri[tid + o];
            if (v < rv[tid] || (v == rv[tid] && ii < ri[tid])) { rv[tid] = v; ri[tid] = ii; }
        }
        __syncthreads();
    }
    if (tid == 0) g_final[row] = ri[0];
}

// ---------------------------------------------------------------------------
// Kernel E: gather + per-block loss partials (deterministic).
// ---------------------------------------------------------------------------
__global__ __launch_bounds__(256) void gather_kernel(const float* __restrict__ cb,
                                                     float* __restrict__ out) {
    __shared__ float sw[8];
    int warp = threadIdx.x >> 5, lane = threadIdx.x & 31;
    int row = blockIdx.x * 8 + warp;
    int ind = g_final[row];
    float4 c = *(const float4*)&cb[(size_t)ind * DIM + lane * 4];
    float4 xv = *(const float4*)&g_xn[(size_t)row * DIM + lane * 4];
    *(float4*)&out[OUT_Q + (size_t)row * DIM + lane * 4] = c;
    float dx = c.x - xv.x, dy = c.y - xv.y, dz = c.z - xv.z, dw = c.w - xv.w;
    float s = dx * dx + dy * dy + dz * dz + dw * dw;
    #pragma unroll
    for (int o = 16; o > 0; o >>= 1) s += __shfl_xor_sync(0xffffffffu, s, o);
    if (lane == 0) { out[OUT_IND + row] = (float)ind; sw[warp] = s; }
    __syncthreads();
    if (threadIdx.x == 0) {
        float tot = 0.0f;
        #pragma unroll
        for (int w = 0; w < 8; w++) tot += sw[w];
        g_part[blockIdx.x] = tot;
    }
}

__global__ __launch_bounds__(256) void final_kernel(float* __restrict__ out) {
    __shared__ float sp[256];
    int tid = threadIdx.x;
    float s = 0.0f;
    for (int i = tid; i < GATHER_BLOCKS; i += 256) s += g_part[i];
    sp[tid] = s;
    __syncthreads();
    for (int o = 128; o > 0; o >>= 1) {
        if (tid < o) sp[tid] += sp[tid + o];
        __syncthreads();
    }
    if (tid == 0) out[OUT_LOSS] = sp[0] * (1.0f / (float)(NROWS * DIM));
}

// ---------------------------------------------------------------------------
extern "C" void kernel_launch(void* const* d_in, const int* in_sizes, int n_in,
                              void* d_out, int out_size) {
    const float* x = (const float*)d_in[0];
    const float* cb = (const float*)d_in[1];
    float* out = (float*)d_out;

    cudaFuncSetAttribute(nn_kernel, cudaFuncAttributeMaxDynamicSharedMemorySize,
                         NN_SMEM);

    ln_kernel<<<NROWS / 8, 256>>>(x);
    cb_kernel<<<KCODES / 8, 256>>>(cb);
    nn_kernel<<<NN_GRID, 256, NN_SMEM>>>();
    combine_kernel<<<NROWS / 256, 256>>>();
    rescan_kernel<<<NROWS, 128>>>(cb);
    gather_kernel<<<GATHER_BLOCKS, 256>>>(cb, out);
    final_kernel<<<1, 256>>>(out);
}